// round 8
// baseline (speedup 1.0000x reference)
#include <cuda_runtime.h>
#include <cstdint>
#include <math.h>

#define BB 2
#define SS 2048
#define DD 1024
#define HH 16
#define HD 64
#define MM (BB*SS)

// ---------------- scratch ---------------------------------------------------
__device__ float g_q[BB*HH*SS*HD];     // q split-head fp32
__device__ float g_apre[BB*SS*DD];     // attention out pre-c_proj [B,S,D]
__device__ float g_linv[BB*HH*SS];     // 1 / softmax denominator per row

// ---------------- helpers ---------------------------------------------------
__device__ __forceinline__ uint32_t cvt_tf32(float x) {
    uint32_t r;
    asm("cvt.rna.tf32.f32 %0, %1;" : "=r"(r) : "f"(x));
    return r;
}
__device__ __forceinline__ void mma_tf32(float* d, const uint32_t* a,
                                         const uint32_t* b) {
    asm volatile("mma.sync.aligned.m16n8k8.row.col.f32.tf32.tf32.f32 "
        "{%0,%1,%2,%3}, {%4,%5,%6,%7}, {%8,%9}, {%0,%1,%2,%3};"
        : "+f"(d[0]), "+f"(d[1]), "+f"(d[2]), "+f"(d[3])
        : "r"(a[0]), "r"(a[1]), "r"(a[2]), "r"(a[3]), "r"(b[0]), "r"(b[1]));
}
__device__ __forceinline__ void cp16(uint32_t s, const void* g) {
    asm volatile("cp.async.cg.shared.global [%0], [%1], 16;"
                 :: "r"(s), "l"(g) : "memory");
}
#define CP_COMMIT() asm volatile("cp.async.commit_group;" ::: "memory")
#define CP_WAIT(n)  asm volatile("cp.async.wait_group %0;" :: "n"(n) : "memory")

// ---------------------------------------------------------------------------
// tf32 GEMM, 3-stage cp.async pipeline. (unchanged from R7)
// ---------------------------------------------------------------------------
#define GS_A (128*36)
#define GS_B (32*132)
#define GEMM_SMEM (3*(GS_A + GS_B)*4)

__global__ __launch_bounds__(256, 2) void gemm_mma(const float* __restrict__ A,
                                                   const float* __restrict__ W,
                                                   const float* __restrict__ bias,
                                                   float* __restrict__ out,
                                                   int split)
{
    extern __shared__ float gsm[];
    float* As = gsm;
    float* Bs = gsm + 3*GS_A;
    int t = threadIdx.x;
    int wid = t >> 5, lane = t & 31;
    int g = lane >> 2, c = lane & 3;
    int warpM = wid >> 2, warpN = wid & 3;
    int m0 = blockIdx.y << 7, n0 = blockIdx.x << 7;

    float acc[4][4][4];
    #pragma unroll
    for (int mi = 0; mi < 4; mi++)
        #pragma unroll
        for (int ni = 0; ni < 4; ni++)
            #pragma unroll
            for (int r = 0; r < 4; r++) acc[mi][ni][r] = 0.0f;

    int ar = t >> 3, aseg = t & 7;
    int br = t >> 5, bseg = t & 31;

    const float* Abase = A + (size_t)(m0 + ar)*DD + aseg*4;
    const float* Wbase = W + (size_t)br*DD + n0 + bseg*4;
    uint32_t sA = (uint32_t)__cvta_generic_to_shared(&As[ar*36 + aseg*4]);
    uint32_t sB = (uint32_t)__cvta_generic_to_shared(&Bs[br*132 + bseg*4]);

    #define G_ISSUE(k0, st) do {                                              \
        _Pragma("unroll")                                                     \
        for (int i = 0; i < 4; i++)                                           \
            cp16(sA + (st)*(GS_A*4) + i*(32*36*4),                            \
                 Abase + (size_t)(32*i)*DD + (k0));                           \
        _Pragma("unroll")                                                     \
        for (int i = 0; i < 4; i++)                                           \
            cp16(sB + (st)*(GS_B*4) + i*(8*132*4),                            \
                 Wbase + (size_t)((k0) + 8*i)*DD);                            \
        CP_COMMIT(); } while (0)

    G_ISSUE(0, 0);
    G_ISSUE(32, 1);

    for (int cc = 0; cc < 32; cc++) {
        if (cc < 31) CP_WAIT(1); else CP_WAIT(0);
        __syncthreads();
        if (cc + 2 < 32) G_ISSUE((cc+2)*32, (cc+2)%3);

        const float* Ac = As + (cc%3)*GS_A;
        const float* Bc = Bs + (cc%3)*GS_B;
        #pragma unroll
        for (int ks = 0; ks < 4; ks++) {
            uint32_t af[4][4], bf[4][2];
            int kc = ks*8 + c;
            #pragma unroll
            for (int mi = 0; mi < 4; mi++) {
                int rb = warpM*64 + mi*16;
                af[mi][0] = cvt_tf32(Ac[(rb+g  )*36 + kc  ]);
                af[mi][1] = cvt_tf32(Ac[(rb+g+8)*36 + kc  ]);
                af[mi][2] = cvt_tf32(Ac[(rb+g  )*36 + kc+4]);
                af[mi][3] = cvt_tf32(Ac[(rb+g+8)*36 + kc+4]);
            }
            #pragma unroll
            for (int ni = 0; ni < 4; ni++) {
                int nb = warpN*32 + ni*8 + g;
                bf[ni][0] = cvt_tf32(Bc[(kc  )*132 + nb]);
                bf[ni][1] = cvt_tf32(Bc[(kc+4)*132 + nb]);
            }
            #pragma unroll
            for (int mi = 0; mi < 4; mi++)
                #pragma unroll
                for (int ni = 0; ni < 4; ni++)
                    mma_tf32(acc[mi][ni], af[mi], bf[ni]);
        }
    }

    #pragma unroll
    for (int mi = 0; mi < 4; mi++) {
        int row0 = m0 + warpM*64 + mi*16 + g;
        #pragma unroll
        for (int ni = 0; ni < 4; ni++) {
            int col = n0 + warpN*32 + ni*8 + 2*c;
            float b0 = bias[col], b1 = bias[col+1];
            float2 v0 = make_float2(acc[mi][ni][0] + b0, acc[mi][ni][1] + b1);
            float2 v1 = make_float2(acc[mi][ni][2] + b0, acc[mi][ni][3] + b1);
            if (split) {
                int h = col >> 6, ho = col & 63;
                int b_ = row0 >> 11, s0 = row0 & 2047;
                *(float2*)&out[((size_t)(b_*HH + h)*SS + s0)*HD + ho] = v0;
                *(float2*)&out[((size_t)(b_*HH + h)*SS + s0 + 8)*HD + ho] = v1;
            } else {
                *(float2*)&out[(size_t)row0*DD + col] = v0;
                *(float2*)&out[(size_t)(row0+8)*DD + col] = v1;
            }
        }
    }
}

// ---------------------------------------------------------------------------
// Pass 1: softmax denominators. QK + exp + row-sum only, K double-buffered.
// Writes 1/l to g_linv. smem 52KB.
// ---------------------------------------------------------------------------
#define SUMS_SMEM (3*64*68*4)

__global__ __launch_bounds__(256, 2) void sums_kernel(const float* __restrict__ kin)
{
    extern __shared__ float sm[];
    float* Qs = sm;                   // 64x68 tf32 bits
    float* Ks = Qs + 64*68;           // [2][64x68]

    int bh = blockIdx.y;
    int qtile = gridDim.x - 1 - blockIdx.x;   // heavy first
    int q0 = qtile << 6;
    int t = threadIdx.x;
    int wid = t >> 5, lane = t & 31;
    int g = lane >> 2, c = lane & 3;
    int warpM = wid >> 2, warpN = wid & 3;

    const float* qb = g_q + (size_t)bh * SS * HD;
    const float* kb = kin + (size_t)bh * SS * HD;

    int seg = t & 15, r0 = t >> 4;
    #pragma unroll
    for (int i = 0; i < 4; i++) {
        int r = r0 + 16*i;
        float4 q4 = *(const float4*)&qb[(size_t)(q0 + r)*HD + seg*4];
        uint4 qt;
        qt.x = cvt_tf32(q4.x); qt.y = cvt_tf32(q4.y);
        qt.z = cvt_tf32(q4.z); qt.w = cvt_tf32(q4.w);
        *(uint4*)&Qs[r*68 + seg*4] = qt;
    }

    uint32_t sK = (uint32_t)__cvta_generic_to_shared(&Ks[r0*68 + seg*4]);
    #define K_ISSUE(kpos0, st) do {                                           \
        _Pragma("unroll")                                                     \
        for (int i = 0; i < 4; i++)                                           \
            cp16(sK + (st)*(64*68*4) + i*(16*68*4),                           \
                 &kb[(size_t)((kpos0) + r0 + 16*i)*HD + seg*4]);              \
        CP_COMMIT(); } while (0)

    float psum[2][2] = {{0.f,0.f},{0.f,0.f}};
    int nkb = qtile + 1;
    K_ISSUE(0, 0);

    for (int kb2 = 0; kb2 < nkb; kb2++) {
        CP_WAIT(0);
        __syncthreads();
        if (kb2 + 1 < nkb) K_ISSUE((kb2+1) << 6, (kb2+1) & 1);
        const float* Kc = Ks + (kb2 & 1)*(64*68);
        int kpos0 = kb2 << 6;

        float S[2][2][4];
        #pragma unroll
        for (int mi = 0; mi < 2; mi++)
            #pragma unroll
            for (int ni = 0; ni < 2; ni++)
                #pragma unroll
                for (int r = 0; r < 4; r++) S[mi][ni][r] = 0.0f;

        #pragma unroll
        for (int ks = 0; ks < 8; ks++) {
            uint32_t af[2][4], bf[2][2];
            int kc = ks*8 + c;
            #pragma unroll
            for (int mi = 0; mi < 2; mi++) {
                int rb = warpM*32 + mi*16;
                af[mi][0] = __float_as_uint(Qs[(rb+g  )*68 + kc  ]);
                af[mi][1] = __float_as_uint(Qs[(rb+g+8)*68 + kc  ]);
                af[mi][2] = __float_as_uint(Qs[(rb+g  )*68 + kc+4]);
                af[mi][3] = __float_as_uint(Qs[(rb+g+8)*68 + kc+4]);
            }
            #pragma unroll
            for (int ni = 0; ni < 2; ni++) {
                int nb = warpN*16 + ni*8 + g;
                bf[ni][0] = cvt_tf32(Kc[nb*68 + kc  ]);
                bf[ni][1] = cvt_tf32(Kc[nb*68 + kc+4]);
            }
            #pragma unroll
            for (int mi = 0; mi < 2; mi++)
                #pragma unroll
                for (int ni = 0; ni < 2; ni++)
                    mma_tf32(S[mi][ni], af[mi], bf[ni]);
        }

        #pragma unroll
        for (int mi = 0; mi < 2; mi++) {
            int row0 = q0 + warpM*32 + mi*16 + g;
            #pragma unroll
            for (int ni = 0; ni < 2; ni++) {
                int key = kpos0 + warpN*16 + ni*8 + 2*c;
                float e00 = (key   <= row0  ) ? __expf(S[mi][ni][0]*0.125f) : 0.f;
                float e01 = (key+1 <= row0  ) ? __expf(S[mi][ni][1]*0.125f) : 0.f;
                float e10 = (key   <= row0+8) ? __expf(S[mi][ni][2]*0.125f) : 0.f;
                float e11 = (key+1 <= row0+8) ? __expf(S[mi][ni][3]*0.125f) : 0.f;
                psum[mi][0] += e00 + e01;
                psum[mi][1] += e10 + e11;
            }
        }
    }
    __syncthreads();

    // reduce: quad lanes, then 4 warpN groups via smem (reuse Ks)
    #pragma unroll
    for (int mi = 0; mi < 2; mi++)
        #pragma unroll
        for (int hh = 0; hh < 2; hh++) {
            float v = psum[mi][hh];
            v += __shfl_xor_sync(0xFFFFFFFF, v, 1);
            v += __shfl_xor_sync(0xFFFFFFFF, v, 2);
            psum[mi][hh] = v;
        }
    if (c == 0) {
        #pragma unroll
        for (int mi = 0; mi < 2; mi++)
            #pragma unroll
            for (int hh = 0; hh < 2; hh++) {
                int lrow = warpM*32 + mi*16 + g + hh*8;
                Ks[lrow*4 + warpN] = psum[mi][hh];
            }
    }
    __syncthreads();
    if (t < 64) {
        float l = Ks[t*4] + Ks[t*4+1] + Ks[t*4+2] + Ks[t*4+3];
        g_linv[(size_t)bh*SS + q0 + t] = 1.0f / l;
    }
}

// ---------------------------------------------------------------------------
// Pass 2: attention. 1/l known -> writes NORMALIZED attnw + zero-fills its
// upper-triangle strip; PV output directly normalized -> g_apre.
// ---------------------------------------------------------------------------
#define ATTN_SMEM (6*64*68*4)

__global__ __launch_bounds__(256, 2) void attn_mma(const float* __restrict__ kin,
                                                   const float* __restrict__ vin,
                                                   float* __restrict__ attnw)
{
    extern __shared__ float sm[];
    float* Qs = sm;                   // 64x68 tf32 bits
    float* Ks = Qs + 64*68;           // [2][64x68]
    float* Vs = Ks + 2*64*68;         // [2][64x68]
    float* Ps = Vs + 2*64*68;         // 64x68 tf32 bits

    int bh = blockIdx.y;
    int qtile = gridDim.x - 1 - blockIdx.x;   // heavy first
    int q0 = qtile << 6;
    int t = threadIdx.x;
    int wid = t >> 5, lane = t & 31;
    int g = lane >> 2, c = lane & 3;
    int warpM = wid >> 2, warpN = wid & 3;

    const float* qb = g_q + (size_t)bh * SS * HD;
    const float* kb = kin + (size_t)bh * SS * HD;
    const float* vb = vin + (size_t)bh * SS * HD;
    float*       wb = attnw + (size_t)bh * SS * SS;

    // zero-fill upper-triangle strip first (stores overlap with compute)
    {
        float4 z = make_float4(0.f, 0.f, 0.f, 0.f);
        int zr = q0 + (t >> 2);
        for (int col = q0 + 64 + (t & 3)*4; col < SS; col += 16)
            *(float4*)&wb[(size_t)zr*SS + col] = z;
    }

    int seg = t & 15, r0 = t >> 4;
    #pragma unroll
    for (int i = 0; i < 4; i++) {
        int r = r0 + 16*i;
        float4 q4 = *(const float4*)&qb[(size_t)(q0 + r)*HD + seg*4];
        uint4 qt;
        qt.x = cvt_tf32(q4.x); qt.y = cvt_tf32(q4.y);
        qt.z = cvt_tf32(q4.z); qt.w = cvt_tf32(q4.w);
        *(uint4*)&Qs[r*68 + seg*4] = qt;
    }

    // per-thread row inverses (from pass 1)
    float inv[2][2];
    #pragma unroll
    for (int mi = 0; mi < 2; mi++) {
        int lrow = warpM*32 + mi*16 + g;
        inv[mi][0] = g_linv[(size_t)bh*SS + q0 + lrow];
        inv[mi][1] = g_linv[(size_t)bh*SS + q0 + lrow + 8];
    }

    uint32_t sK = (uint32_t)__cvta_generic_to_shared(&Ks[r0*68 + seg*4]);
    uint32_t sV = (uint32_t)__cvta_generic_to_shared(&Vs[r0*68 + seg*4]);
    #define KV_ISSUE(kpos0, st) do {                                          \
        _Pragma("unroll")                                                     \
        for (int i = 0; i < 4; i++) {                                         \
            int r = r0 + 16*i;                                                \
            cp16(sK + (st)*(64*68*4) + i*(16*68*4),                           \
                 &kb[(size_t)((kpos0) + r)*HD + seg*4]);                      \
            cp16(sV + (st)*(64*68*4) + i*(16*68*4),                           \
                 &vb[(size_t)((kpos0) + r)*HD + seg*4]);                      \
        }                                                                     \
        CP_COMMIT(); } while (0)

    float O[2][2][4];
    #pragma unroll
    for (int mi = 0; mi < 2; mi++)
        #pragma unroll
        for (int ni = 0; ni < 2; ni++)
            #pragma unroll
            for (int r = 0; r < 4; r++) O[mi][ni][r] = 0.0f;

    int nkb = qtile + 1;
    KV_ISSUE(0, 0);

    for (int kb2 = 0; kb2 < nkb; kb2++) {
        CP_WAIT(0);
        __syncthreads();
        if (kb2 + 1 < nkb) KV_ISSUE((kb2+1) << 6, (kb2+1) & 1);

        const float* Kc = Ks + (kb2 & 1)*(64*68);
        const float* Vc = Vs + (kb2 & 1)*(64*68);
        int kpos0 = kb2 << 6;

        float S[2][2][4];
        #pragma unroll
        for (int mi = 0; mi < 2; mi++)
            #pragma unroll
            for (int ni = 0; ni < 2; ni++)
                #pragma unroll
                for (int r = 0; r < 4; r++) S[mi][ni][r] = 0.0f;

        #pragma unroll
        for (int ks = 0; ks < 8; ks++) {
            uint32_t af[2][4], bf[2][2];
            int kc = ks*8 + c;
            #pragma unroll
            for (int mi = 0; mi < 2; mi++) {
                int rb = warpM*32 + mi*16;
                af[mi][0] = __float_as_uint(Qs[(rb+g  )*68 + kc  ]);
                af[mi][1] = __float_as_uint(Qs[(rb+g+8)*68 + kc  ]);
                af[mi][2] = __float_as_uint(Qs[(rb+g  )*68 + kc+4]);
                af[mi][3] = __float_as_uint(Qs[(rb+g+8)*68 + kc+4]);
            }
            #pragma unroll
            for (int ni = 0; ni < 2; ni++) {
                int nb = warpN*16 + ni*8 + g;
                bf[ni][0] = cvt_tf32(Kc[nb*68 + kc  ]);   // K^T[kc][nb]
                bf[ni][1] = cvt_tf32(Kc[nb*68 + kc+4]);
            }
            #pragma unroll
            for (int mi = 0; mi < 2; mi++)
                #pragma unroll
                for (int ni = 0; ni < 2; ni++)
                    mma_tf32(S[mi][ni], af[mi], bf[ni]);
        }

        // exp + mask + normalize; store to attnw and Ps (tf32 bits)
        #pragma unroll
        for (int mi = 0; mi < 2; mi++) {
            int lrow = warpM*32 + mi*16 + g;
            int row0 = q0 + lrow;
            float i0 = inv[mi][0], i1 = inv[mi][1];
            #pragma unroll
            for (int ni = 0; ni < 2; ni++) {
                int lkey = warpN*16 + ni*8 + 2*c;
                int key = kpos0 + lkey;
                float e00 = (key   <= row0  ) ? __expf(S[mi][ni][0]*0.125f)*i0 : 0.f;
                float e01 = (key+1 <= row0  ) ? __expf(S[mi][ni][1]*0.125f)*i0 : 0.f;
                float e10 = (key   <= row0+8) ? __expf(S[mi][ni][2]*0.125f)*i1 : 0.f;
                float e11 = (key+1 <= row0+8) ? __expf(S[mi][ni][3]*0.125f)*i1 : 0.f;
                *(float2*)&wb[(size_t)row0*SS + key]     = make_float2(e00, e01);
                *(float2*)&wb[(size_t)(row0+8)*SS + key] = make_float2(e10, e11);
                *(uint2*)&Ps[lrow*68 + lkey]     = make_uint2(cvt_tf32(e00), cvt_tf32(e01));
                *(uint2*)&Ps[(lrow+8)*68 + lkey] = make_uint2(cvt_tf32(e10), cvt_tf32(e11));
            }
        }
        __syncthreads();

        // O += P V
        #pragma unroll
        for (int ks = 0; ks < 8; ks++) {
            uint32_t af[2][4], bf[2][2];
            int kc = ks*8 + c;
            #pragma unroll
            for (int mi = 0; mi < 2; mi++) {
                int rb = warpM*32 + mi*16;
                af[mi][0] = __float_as_uint(Ps[(rb+g  )*68 + kc  ]);
                af[mi][1] = __float_as_uint(Ps[(rb+g+8)*68 + kc  ]);
                af[mi][2] = __float_as_uint(Ps[(rb+g  )*68 + kc+4]);
                af[mi][3] = __float_as_uint(Ps[(rb+g+8)*68 + kc+4]);
            }
            #pragma unroll
            for (int ni = 0; ni < 2; ni++) {
                int nb = warpN*16 + ni*8 + g;
                bf[ni][0] = cvt_tf32(Vc[(kc  )*68 + nb]);
                bf[ni][1] = cvt_tf32(Vc[(kc+4)*68 + nb]);
            }
            #pragma unroll
            for (int mi = 0; mi < 2; mi++)
                #pragma unroll
                for (int ni = 0; ni < 2; ni++)
                    mma_tf32(O[mi][ni], af[mi], bf[ni]);
        }
        // next iteration's top barrier protects Ps/K/V reuse
    }

    // output (already normalized) -> g_apre [B,S,D]
    int b_ = bh >> 4, h = bh & 15;
    #pragma unroll
    for (int mi = 0; mi < 2; mi++) {
        int lrow = warpM*32 + mi*16 + g;
        int s0 = q0 + lrow;
        #pragma unroll
        for (int ni = 0; ni < 2; ni++) {
            int n = warpN*16 + ni*8 + 2*c;
            float* p0 = &g_apre[((size_t)b_*SS + s0)*DD + h*HD + n];
            float* p1 = &g_apre[((size_t)b_*SS + s0 + 8)*DD + h*HD + n];
            *(float2*)p0 = make_float2(O[mi][ni][0], O[mi][ni][1]);
            *(float2*)p1 = make_float2(O[mi][ni][2], O[mi][ni][3]);
        }
    }
}

// ---------------------------------------------------------------------------
extern "C" void kernel_launch(void* const* d_in, const int* in_sizes, int n_in,
                              void* d_out, int out_size)
{
    const float* hs = (const float*)d_in[0];
    const float* wq = (const float*)d_in[1];
    const float* bq = (const float*)d_in[2];
    const float* wk = (const float*)d_in[3];
    const float* bk = (const float*)d_in[4];
    const float* wv = (const float*)d_in[5];
    const float* bv = (const float*)d_in[6];
    const float* wc = (const float*)d_in[7];
    const float* bc = (const float*)d_in[8];

    float* out      = (float*)d_out;
    float* out_attn = out;                                   // [B,S,D]
    float* out_w    = out + (size_t)BB*SS*DD;                // [B,H,S,S]
    float* out_k    = out_w + (size_t)BB*HH*SS*SS;           // [B,H,S,hd]
    float* out_v    = out_k + (size_t)BB*HH*SS*HD;           // [B,H,S,hd]

    float *qptr, *aptr;
    cudaGetSymbolAddress((void**)&qptr, g_q);
    cudaGetSymbolAddress((void**)&aptr, g_apre);

    cudaFuncSetAttribute(gemm_mma,
                         cudaFuncAttributeMaxDynamicSharedMemorySize, GEMM_SMEM);
    cudaFuncSetAttribute(sums_kernel,
                         cudaFuncAttributeMaxDynamicSharedMemorySize, SUMS_SMEM);
    cudaFuncSetAttribute(attn_mma,
                         cudaFuncAttributeMaxDynamicSharedMemorySize, ATTN_SMEM);

    dim3 gg(DD/128, MM/128);   // (8, 32)
    gemm_mma<<<gg, 256, GEMM_SMEM>>>(hs, wq, bq, qptr, 1);
    gemm_mma<<<gg, 256, GEMM_SMEM>>>(hs, wk, bk, out_k, 1);
    gemm_mma<<<gg, 256, GEMM_SMEM>>>(hs, wv, bv, out_v, 1);

    sums_kernel<<<dim3(SS/64, BB*HH), 256, SUMS_SMEM>>>(out_k);
    attn_mma<<<dim3(SS/64, BB*HH), 256, ATTN_SMEM>>>(out_k, out_v, out_w);

    gemm_mma<<<gg, 256, GEMM_SMEM>>>(aptr, wc, bc, out_attn, 0);
}

// round 9
// speedup vs baseline: 1.6659x; 1.6659x over previous
#include <cuda_runtime.h>
#include <cuda_fp16.h>
#include <cstdint>
#include <math.h>

#define BB 2
#define SS 2048
#define DD 1024
#define HH 16
#define HD 64
#define MM (BB*SS)

// ---------------- scratch (fp16 operand copies; fp32 stats) -----------------
__device__ __half g_hsh[MM*DD];        // hs fp16 [m][k]
__device__ __half g_wt[4*DD*DD];       // W^T fp16 [n][k] for q,k,v,c
__device__ __half g_qh[BB*HH*SS*HD];   // q fp16 split-head
__device__ __half g_kh[BB*HH*SS*HD];   // k fp16 split-head
__device__ __half g_vh[BB*HH*SS*HD];   // v fp16 split-head
__device__ __half g_apreh[MM*DD];      // attention out pre-c_proj fp16 [m][k]
__device__ float  g_linv[BB*HH*SS];    // 1 / softmax denominator

// ---------------- helpers ---------------------------------------------------
__device__ __forceinline__ void mma_f16(float* d, const uint32_t* a,
                                        const uint32_t* b) {
    asm volatile("mma.sync.aligned.m16n8k16.row.col.f32.f16.f16.f32 "
        "{%0,%1,%2,%3}, {%4,%5,%6,%7}, {%8,%9}, {%0,%1,%2,%3};"
        : "+f"(d[0]), "+f"(d[1]), "+f"(d[2]), "+f"(d[3])
        : "r"(a[0]), "r"(a[1]), "r"(a[2]), "r"(a[3]), "r"(b[0]), "r"(b[1]));
}
__device__ __forceinline__ void ldsm2t(uint32_t& r0, uint32_t& r1, uint32_t sa) {
    asm volatile("ldmatrix.sync.aligned.m8n8.x2.trans.shared.b16 {%0,%1}, [%2];"
                 : "=r"(r0), "=r"(r1) : "r"(sa));
}
__device__ __forceinline__ void cp16(uint32_t s, const void* g) {
    asm volatile("cp.async.cg.shared.global [%0], [%1], 16;"
                 :: "r"(s), "l"(g) : "memory");
}
#define CP_COMMIT() asm volatile("cp.async.commit_group;" ::: "memory")
#define CP_WAIT(n)  asm volatile("cp.async.wait_group %0;" :: "n"(n) : "memory")
__device__ __forceinline__ uint32_t pack_h2(float a, float b) {
    __half2 h = __floats2half2_rn(a, b);
    return *(uint32_t*)&h;
}

// ---------------------------------------------------------------------------
// fp32 -> fp16 elementwise (float4 granularity)
// ---------------------------------------------------------------------------
__global__ __launch_bounds__(256) void conv_h(const float* __restrict__ x,
                                              __half* __restrict__ y)
{
    int i = blockIdx.x * 256 + threadIdx.x;
    float4 v = ((const float4*)x)[i];
    ((uint2*)y)[i] = make_uint2(pack_h2(v.x, v.y), pack_h2(v.z, v.w));
}

// ---------------------------------------------------------------------------
// transpose + convert: W[k][n] fp32 -> Wt[n][k] fp16
// ---------------------------------------------------------------------------
__global__ __launch_bounds__(256) void tconv_h(const float* __restrict__ W,
                                               __half* __restrict__ Wt)
{
    __shared__ float tile[32][33];
    int tx = threadIdx.x & 31, ty = threadIdx.x >> 5;
    int k0 = blockIdx.y << 5, n0 = blockIdx.x << 5;
    #pragma unroll
    for (int i = 0; i < 4; i++)
        tile[ty + 8*i][tx] = W[(size_t)(k0 + ty + 8*i)*DD + n0 + tx];
    __syncthreads();
    #pragma unroll
    for (int i = 0; i < 4; i++)
        Wt[(size_t)(n0 + ty + 8*i)*DD + k0 + tx] = __float2half(tile[tx][ty + 8*i]);
}

// ---------------------------------------------------------------------------
// fp16 GEMM, 3-stage cp.async. Block 128x128, 8 warps (2Mx4N), warp 64x32,
// K-chunk 32 (2 x k16). A fp16 [m][k]; B = Wt fp16 [n][k].
// outf32 (optional): fp32 + bias, split/linear; outh (optional): fp16 split-head.
// ---------------------------------------------------------------------------
#define GS_T (128*40)                      // halfs per tile-stage
#define GEMM_SMEM (3*2*GS_T*2)             // bytes

__global__ __launch_bounds__(256, 2) void gemm_h(const __half* __restrict__ A,
                                                 const __half* __restrict__ Wt,
                                                 const float* __restrict__ bias,
                                                 float* __restrict__ outf32,
                                                 __half* __restrict__ outh,
                                                 int split)
{
    extern __shared__ __half hsm[];
    __half* As = hsm;                      // [3][128*40]
    __half* Bs = hsm + 3*GS_T;             // [3][128*40]
    int t = threadIdx.x;
    int wid = t >> 5, lane = t & 31;
    int g = lane >> 2, c = lane & 3;
    int warpM = wid >> 2, warpN = wid & 3;
    int m0 = blockIdx.y << 7, n0 = blockIdx.x << 7;

    float acc[4][4][4];
    #pragma unroll
    for (int mi = 0; mi < 4; mi++)
        #pragma unroll
        for (int ni = 0; ni < 4; ni++)
            #pragma unroll
            for (int r = 0; r < 4; r++) acc[mi][ni][r] = 0.0f;

    int lr = t >> 2, lseg = t & 3;         // rows lr, lr+64; 4 segs x 8 halfs
    const __half* Abase = A  + (size_t)(m0 + lr)*DD + lseg*8;
    const __half* Bbase = Wt + (size_t)(n0 + lr)*DD + lseg*8;
    uint32_t sA = (uint32_t)__cvta_generic_to_shared(&As[lr*40 + lseg*8]);
    uint32_t sB = (uint32_t)__cvta_generic_to_shared(&Bs[lr*40 + lseg*8]);

    #define G_ISSUE(k0c, st) do {                                             \
        cp16(sA + (st)*(GS_T*2),             Abase + (k0c));                  \
        cp16(sA + (st)*(GS_T*2) + 64*40*2,   Abase + (size_t)64*DD + (k0c));  \
        cp16(sB + (st)*(GS_T*2),             Bbase + (k0c));                  \
        cp16(sB + (st)*(GS_T*2) + 64*40*2,   Bbase + (size_t)64*DD + (k0c));  \
        CP_COMMIT(); } while (0)

    G_ISSUE(0, 0);
    G_ISSUE(32, 1);

    for (int cc = 0; cc < 32; cc++) {
        if (cc < 31) CP_WAIT(1); else CP_WAIT(0);
        __syncthreads();
        if (cc + 2 < 32) G_ISSUE((cc+2)*32, (cc+2)%3);

        const __half* Ac = As + (cc%3)*GS_T;
        const __half* Bc = Bs + (cc%3)*GS_T;
        #pragma unroll
        for (int ks = 0; ks < 2; ks++) {
            uint32_t af[4][4], bf[4][2];
            int kc = ks*16 + 2*c;
            #pragma unroll
            for (int mi = 0; mi < 4; mi++) {
                int rb = warpM*64 + mi*16;
                af[mi][0] = *(const uint32_t*)&Ac[(rb+g  )*40 + kc    ];
                af[mi][1] = *(const uint32_t*)&Ac[(rb+g+8)*40 + kc    ];
                af[mi][2] = *(const uint32_t*)&Ac[(rb+g  )*40 + kc + 8];
                af[mi][3] = *(const uint32_t*)&Ac[(rb+g+8)*40 + kc + 8];
            }
            #pragma unroll
            for (int ni = 0; ni < 4; ni++) {
                int nb = warpN*32 + ni*8 + g;
                bf[ni][0] = *(const uint32_t*)&Bc[nb*40 + kc    ];
                bf[ni][1] = *(const uint32_t*)&Bc[nb*40 + kc + 8];
            }
            #pragma unroll
            for (int mi = 0; mi < 4; mi++)
                #pragma unroll
                for (int ni = 0; ni < 4; ni++)
                    mma_f16(acc[mi][ni], af[mi], bf[ni]);
        }
    }

    // epilogue
    #pragma unroll
    for (int mi = 0; mi < 4; mi++) {
        int row0 = m0 + warpM*64 + mi*16 + g;
        int b_ = row0 >> 11, s0 = row0 & 2047;
        #pragma unroll
        for (int ni = 0; ni < 4; ni++) {
            int col = n0 + warpN*32 + ni*8 + 2*c;
            float b0 = bias[col], b1 = bias[col+1];
            float2 v0 = make_float2(acc[mi][ni][0] + b0, acc[mi][ni][1] + b1);
            float2 v1 = make_float2(acc[mi][ni][2] + b0, acc[mi][ni][3] + b1);
            int h = col >> 6, ho = col & 63;
            if (outf32) {
                if (split) {
                    *(float2*)&outf32[((size_t)(b_*HH + h)*SS + s0)*HD + ho] = v0;
                    *(float2*)&outf32[((size_t)(b_*HH + h)*SS + s0 + 8)*HD + ho] = v1;
                } else {
                    *(float2*)&outf32[(size_t)row0*DD + col] = v0;
                    *(float2*)&outf32[(size_t)(row0+8)*DD + col] = v1;
                }
            }
            if (outh) {
                *(uint32_t*)&outh[((size_t)(b_*HH + h)*SS + s0)*HD + ho] =
                    pack_h2(v0.x, v0.y);
                *(uint32_t*)&outh[((size_t)(b_*HH + h)*SS + s0 + 8)*HD + ho] =
                    pack_h2(v1.x, v1.y);
            }
        }
    }
}

// ---------------------------------------------------------------------------
// Pass 1: softmax denominators (fp16 QK + exp + row sum). K double-buffered.
// ---------------------------------------------------------------------------
#define AT_T (64*72)                       // halfs per attn tile
#define SUMS_SMEM (3*AT_T*2)

__global__ __launch_bounds__(256, 2) void sums_kernel(const __half* __restrict__ kin)
{
    extern __shared__ __half hsm[];
    __half* Qs = hsm;                      // 64x72
    __half* Ks = hsm + AT_T;               // [2][64x72]

    int bh = blockIdx.y;
    int qtile = gridDim.x - 1 - blockIdx.x;
    int q0 = qtile << 6;
    int t = threadIdx.x;
    int wid = t >> 5, lane = t & 31;
    int g = lane >> 2, c = lane & 3;
    int warpM = wid >> 2, warpN = wid & 3;

    const __half* qb = g_qh + (size_t)bh * SS * HD;
    const __half* kb = kin  + (size_t)bh * SS * HD;

    int lr = t >> 3, lseg = t & 7;         // rows lr, lr+32; 8 segs x 8 halfs
    uint32_t sQ = (uint32_t)__cvta_generic_to_shared(&Qs[lr*72 + lseg*8]);
    uint32_t sK = (uint32_t)__cvta_generic_to_shared(&Ks[lr*72 + lseg*8]);

    cp16(sQ,           &qb[(size_t)(q0 + lr)*HD + lseg*8]);
    cp16(sQ + 32*72*2, &qb[(size_t)(q0 + lr + 32)*HD + lseg*8]);

    #define K_ISSUE(kpos0, st) do {                                           \
        cp16(sK + (st)*(AT_T*2),            &kb[(size_t)((kpos0)+lr)*HD + lseg*8]);      \
        cp16(sK + (st)*(AT_T*2) + 32*72*2,  &kb[(size_t)((kpos0)+lr+32)*HD + lseg*8]);   \
        CP_COMMIT(); } while (0)

    float psum[2][2] = {{0.f,0.f},{0.f,0.f}};
    int nkb = qtile + 1;
    K_ISSUE(0, 0);

    for (int kb2 = 0; kb2 < nkb; kb2++) {
        CP_WAIT(0);
        __syncthreads();
        if (kb2 + 1 < nkb) K_ISSUE((kb2+1) << 6, (kb2+1) & 1);
        const __half* Kc = Ks + (kb2 & 1)*AT_T;
        int kpos0 = kb2 << 6;

        float S[2][2][4];
        #pragma unroll
        for (int mi = 0; mi < 2; mi++)
            #pragma unroll
            for (int ni = 0; ni < 2; ni++)
                #pragma unroll
                for (int r = 0; r < 4; r++) S[mi][ni][r] = 0.0f;

        #pragma unroll
        for (int ks = 0; ks < 4; ks++) {       // k16 over hd=64
            uint32_t af[2][4], bf[2][2];
            int kc = ks*16 + 2*c;
            #pragma unroll
            for (int mi = 0; mi < 2; mi++) {
                int rb = warpM*32 + mi*16;
                af[mi][0] = *(const uint32_t*)&Qs[(rb+g  )*72 + kc    ];
                af[mi][1] = *(const uint32_t*)&Qs[(rb+g+8)*72 + kc    ];
                af[mi][2] = *(const uint32_t*)&Qs[(rb+g  )*72 + kc + 8];
                af[mi][3] = *(const uint32_t*)&Qs[(rb+g+8)*72 + kc + 8];
            }
            #pragma unroll
            for (int ni = 0; ni < 2; ni++) {
                int nb = warpN*16 + ni*8 + g;
                bf[ni][0] = *(const uint32_t*)&Kc[nb*72 + kc    ];
                bf[ni][1] = *(const uint32_t*)&Kc[nb*72 + kc + 8];
            }
            #pragma unroll
            for (int mi = 0; mi < 2; mi++)
                #pragma unroll
                for (int ni = 0; ni < 2; ni++)
                    mma_f16(S[mi][ni], af[mi], bf[ni]);
        }

        #pragma unroll
        for (int mi = 0; mi < 2; mi++) {
            int row0 = q0 + warpM*32 + mi*16 + g;
            #pragma unroll
            for (int ni = 0; ni < 2; ni++) {
                int key = kpos0 + warpN*16 + ni*8 + 2*c;
                float e00 = (key   <= row0  ) ? __expf(S[mi][ni][0]*0.125f) : 0.f;
                float e01 = (key+1 <= row0  ) ? __expf(S[mi][ni][1]*0.125f) : 0.f;
                float e10 = (key   <= row0+8) ? __expf(S[mi][ni][2]*0.125f) : 0.f;
                float e11 = (key+1 <= row0+8) ? __expf(S[mi][ni][3]*0.125f) : 0.f;
                psum[mi][0] += e00 + e01;
                psum[mi][1] += e10 + e11;
            }
        }
    }
    __syncthreads();

    float* red = (float*)Ks;
    #pragma unroll
    for (int mi = 0; mi < 2; mi++)
        #pragma unroll
        for (int hh = 0; hh < 2; hh++) {
            float v = psum[mi][hh];
            v += __shfl_xor_sync(0xFFFFFFFF, v, 1);
            v += __shfl_xor_sync(0xFFFFFFFF, v, 2);
            psum[mi][hh] = v;
        }
    if (c == 0) {
        #pragma unroll
        for (int mi = 0; mi < 2; mi++)
            #pragma unroll
            for (int hh = 0; hh < 2; hh++) {
                int lrow = warpM*32 + mi*16 + g + hh*8;
                red[lrow*4 + warpN] = psum[mi][hh];
            }
    }
    __syncthreads();
    if (t < 64) {
        float l = red[t*4] + red[t*4+1] + red[t*4+2] + red[t*4+3];
        g_linv[(size_t)bh*SS + q0 + t] = 1.0f / l;
    }
}

// ---------------------------------------------------------------------------
// Pass 2: attention. Normalized attnw (fp32) + zero-filled triangle;
// normalized PV -> fp16 g_apreh. All mma operands fp16.
// ---------------------------------------------------------------------------
#define ATTN_SMEM (6*AT_T*2)

__global__ __launch_bounds__(256, 2) void attn_mma(const __half* __restrict__ kin,
                                                   const __half* __restrict__ vin,
                                                   float* __restrict__ attnw)
{
    extern __shared__ __half hsm[];
    __half* Qs = hsm;                      // 64x72
    __half* Ks = hsm + AT_T;               // [2][64x72]
    __half* Vs = hsm + 3*AT_T;             // [2][64x72]
    __half* Ps = hsm + 5*AT_T;             // 64x72

    int bh = blockIdx.y;
    int qtile = gridDim.x - 1 - blockIdx.x;
    int q0 = qtile << 6;
    int t = threadIdx.x;
    int wid = t >> 5, lane = t & 31;
    int g = lane >> 2, c = lane & 3;
    int warpM = wid >> 2, warpN = wid & 3;

    const __half* qb = g_qh + (size_t)bh * SS * HD;
    const __half* kb = kin  + (size_t)bh * SS * HD;
    const __half* vb = vin  + (size_t)bh * SS * HD;
    float*        wb = attnw + (size_t)bh * SS * SS;

    // zero-fill upper triangle strip (overlaps with compute)
    {
        float4 z = make_float4(0.f, 0.f, 0.f, 0.f);
        int zr = q0 + (t >> 2);
        for (int col = q0 + 64 + (t & 3)*4; col < SS; col += 16)
            *(float4*)&wb[(size_t)zr*SS + col] = z;
    }

    int lr = t >> 3, lseg = t & 7;
    uint32_t sQ = (uint32_t)__cvta_generic_to_shared(&Qs[lr*72 + lseg*8]);
    uint32_t sK = (uint32_t)__cvta_generic_to_shared(&Ks[lr*72 + lseg*8]);
    uint32_t sV = (uint32_t)__cvta_generic_to_shared(&Vs[lr*72 + lseg*8]);

    cp16(sQ,           &qb[(size_t)(q0 + lr)*HD + lseg*8]);
    cp16(sQ + 32*72*2, &qb[(size_t)(q0 + lr + 32)*HD + lseg*8]);

    #define KV_ISSUE(kpos0, st) do {                                          \
        cp16(sK + (st)*(AT_T*2),           &kb[(size_t)((kpos0)+lr)*HD + lseg*8]);     \
        cp16(sK + (st)*(AT_T*2) + 32*72*2, &kb[(size_t)((kpos0)+lr+32)*HD + lseg*8]);  \
        cp16(sV + (st)*(AT_T*2),           &vb[(size_t)((kpos0)+lr)*HD + lseg*8]);     \
        cp16(sV + (st)*(AT_T*2) + 32*72*2, &vb[(size_t)((kpos0)+lr+32)*HD + lseg*8]);  \
        CP_COMMIT(); } while (0)

    float inv[2][2];
    #pragma unroll
    for (int mi = 0; mi < 2; mi++) {
        int lrow = warpM*32 + mi*16 + g;
        inv[mi][0] = g_linv[(size_t)bh*SS + q0 + lrow];
        inv[mi][1] = g_linv[(size_t)bh*SS + q0 + lrow + 8];
    }

    float O[2][2][4];
    #pragma unroll
    for (int mi = 0; mi < 2; mi++)
        #pragma unroll
        for (int ni = 0; ni < 2; ni++)
            #pragma unroll
            for (int r = 0; r < 4; r++) O[mi][ni][r] = 0.0f;

    int nkb = qtile + 1;
    KV_ISSUE(0, 0);

    for (int kb2 = 0; kb2 < nkb; kb2++) {
        CP_WAIT(0);
        __syncthreads();
        if (kb2 + 1 < nkb) KV_ISSUE((kb2+1) << 6, (kb2+1) & 1);

        const __half* Kc = Ks + (kb2 & 1)*AT_T;
        const __half* Vc = Vs + (kb2 & 1)*AT_T;
        int kpos0 = kb2 << 6;

        float S[2][2][4];
        #pragma unroll
        for (int mi = 0; mi < 2; mi++)
            #pragma unroll
            for (int ni = 0; ni < 2; ni++)
                #pragma unroll
                for (int r = 0; r < 4; r++) S[mi][ni][r] = 0.0f;

        #pragma unroll
        for (int ks = 0; ks < 4; ks++) {       // k16 over hd=64
            uint32_t af[2][4], bf[2][2];
            int kc = ks*16 + 2*c;
            #pragma unroll
            for (int mi = 0; mi < 2; mi++) {
                int rb = warpM*32 + mi*16;
                af[mi][0] = *(const uint32_t*)&Qs[(rb+g  )*72 + kc    ];
                af[mi][1] = *(const uint32_t*)&Qs[(rb+g+8)*72 + kc    ];
                af[mi][2] = *(const uint32_t*)&Qs[(rb+g  )*72 + kc + 8];
                af[mi][3] = *(const uint32_t*)&Qs[(rb+g+8)*72 + kc + 8];
            }
            #pragma unroll
            for (int ni = 0; ni < 2; ni++) {
                int nb = warpN*16 + ni*8 + g;
                bf[ni][0] = *(const uint32_t*)&Kc[nb*72 + kc    ];
                bf[ni][1] = *(const uint32_t*)&Kc[nb*72 + kc + 8];
            }
            #pragma unroll
            for (int mi = 0; mi < 2; mi++)
                #pragma unroll
                for (int ni = 0; ni < 2; ni++)
                    mma_f16(S[mi][ni], af[mi], bf[ni]);
        }

        // exp + mask + normalize; fp32 -> attnw, fp16 pairs -> Ps
        #pragma unroll
        for (int mi = 0; mi < 2; mi++) {
            int lrow = warpM*32 + mi*16 + g;
            int row0 = q0 + lrow;
            float i0 = inv[mi][0], i1 = inv[mi][1];
            #pragma unroll
            for (int ni = 0; ni < 2; ni++) {
                int lkey = warpN*16 + ni*8 + 2*c;
                int key = kpos0 + lkey;
                float e00 = (key   <= row0  ) ? __expf(S[mi][ni][0]*0.125f)*i0 : 0.f;
                float e01 = (key+1 <= row0  ) ? __expf(S[mi][ni][1]*0.125f)*i0 : 0.f;
                float e10 = (key   <= row0+8) ? __expf(S[mi][ni][2]*0.125f)*i1 : 0.f;
                float e11 = (key+1 <= row0+8) ? __expf(S[mi][ni][3]*0.125f)*i1 : 0.f;
                *(float2*)&wb[(size_t)row0*SS + key]     = make_float2(e00, e01);
                *(float2*)&wb[(size_t)(row0+8)*SS + key] = make_float2(e10, e11);
                *(uint32_t*)&Ps[lrow*72 + lkey]     = pack_h2(e00, e01);
                *(uint32_t*)&Ps[(lrow+8)*72 + lkey] = pack_h2(e10, e11);
            }
        }
        __syncthreads();

        // O += P V  (A = Ps fp16 [q][key]; B = V via ldmatrix.trans)
        #pragma unroll
        for (int ks = 0; ks < 4; ks++) {       // k16 over 64 keys
            uint32_t af[2][4], bf[2][2];
            int kc = ks*16 + 2*c;
            #pragma unroll
            for (int mi = 0; mi < 2; mi++) {
                int rb = warpM*32 + mi*16;
                af[mi][0] = *(const uint32_t*)&Ps[(rb+g  )*72 + kc    ];
                af[mi][1] = *(const uint32_t*)&Ps[(rb+g+8)*72 + kc    ];
                af[mi][2] = *(const uint32_t*)&Ps[(rb+g  )*72 + kc + 8];
                af[mi][3] = *(const uint32_t*)&Ps[(rb+g+8)*72 + kc + 8];
            }
            #pragma unroll
            for (int ni = 0; ni < 2; ni++) {
                int n0v = warpN*16 + ni*8;
                uint32_t sa = (uint32_t)__cvta_generic_to_shared(
                    &Vc[(ks*16 + (lane & 15))*72 + n0v]);
                ldsm2t(bf[ni][0], bf[ni][1], sa);
            }
            #pragma unroll
            for (int mi = 0; mi < 2; mi++)
                #pragma unroll
                for (int ni = 0; ni < 2; ni++)
                    mma_f16(O[mi][ni], af[mi], bf[ni]);
        }
        // next iteration's top barrier protects Ps/K/V reuse
    }

    // output (normalized) -> fp16 g_apreh [B,S,D]
    int b_ = bh >> 4, h = bh & 15;
    #pragma unroll
    for (int mi = 0; mi < 2; mi++) {
        int lrow = warpM*32 + mi*16 + g;
        int s0 = q0 + lrow;
        #pragma unroll
        for (int ni = 0; ni < 2; ni++) {
            int n = warpN*16 + ni*8 + 2*c;
            *(uint32_t*)&g_apreh[((size_t)b_*SS + s0)*DD + h*HD + n] =
                pack_h2(O[mi][ni][0], O[mi][ni][1]);
            *(uint32_t*)&g_apreh[((size_t)b_*SS + s0 + 8)*DD + h*HD + n] =
                pack_h2(O[mi][ni][2], O[mi][ni][3]);
        }
    }
}

// ---------------------------------------------------------------------------
extern "C" void kernel_launch(void* const* d_in, const int* in_sizes, int n_in,
                              void* d_out, int out_size)
{
    const float* hs = (const float*)d_in[0];
    const float* wq = (const float*)d_in[1];
    const float* bq = (const float*)d_in[2];
    const float* wk = (const float*)d_in[3];
    const float* bk = (const float*)d_in[4];
    const float* wv = (const float*)d_in[5];
    const float* bv = (const float*)d_in[6];
    const float* wc = (const float*)d_in[7];
    const float* bc = (const float*)d_in[8];

    float* out      = (float*)d_out;
    float* out_attn = out;                                   // [B,S,D]
    float* out_w    = out + (size_t)BB*SS*DD;                // [B,H,S,S]
    float* out_k    = out_w + (size_t)BB*HH*SS*SS;           // [B,H,S,hd]
    float* out_v    = out_k + (size_t)BB*HH*SS*HD;           // [B,H,S,hd]

    __half *hsh, *wt, *qh, *kh, *vh, *apreh;
    cudaGetSymbolAddress((void**)&hsh,   g_hsh);
    cudaGetSymbolAddress((void**)&wt,    g_wt);
    cudaGetSymbolAddress((void**)&qh,    g_qh);
    cudaGetSymbolAddress((void**)&kh,    g_kh);
    cudaGetSymbolAddress((void**)&vh,    g_vh);
    cudaGetSymbolAddress((void**)&apreh, g_apreh);

    cudaFuncSetAttribute(gemm_h,
                         cudaFuncAttributeMaxDynamicSharedMemorySize, GEMM_SMEM);
    cudaFuncSetAttribute(sums_kernel,
                         cudaFuncAttributeMaxDynamicSharedMemorySize, SUMS_SMEM);
    cudaFuncSetAttribute(attn_mma,
                         cudaFuncAttributeMaxDynamicSharedMemorySize, ATTN_SMEM);

    // fp16 conversions
    conv_h<<<(MM*DD/4)/256, 256>>>(hs, hsh);
    dim3 tg(DD/32, DD/32);
    tconv_h<<<tg, 256>>>(wq, wt + 0*(size_t)DD*DD);
    tconv_h<<<tg, 256>>>(wk, wt + 1*(size_t)DD*DD);
    tconv_h<<<tg, 256>>>(wv, wt + 2*(size_t)DD*DD);
    tconv_h<<<tg, 256>>>(wc, wt + 3*(size_t)DD*DD);

    dim3 gg(DD/128, MM/128);   // (8, 32)
    gemm_h<<<gg, 256, GEMM_SMEM>>>(hsh, wt + 0*(size_t)DD*DD, bq, nullptr, qh, 1);
    gemm_h<<<gg, 256, GEMM_SMEM>>>(hsh, wt + 1*(size_t)DD*DD, bk, out_k, kh, 1);
    gemm_h<<<gg, 256, GEMM_SMEM>>>(hsh, wt + 2*(size_t)DD*DD, bv, out_v, vh, 1);

    sums_kernel<<<dim3(SS/64, BB*HH), 256, SUMS_SMEM>>>(kh);
    attn_mma<<<dim3(SS/64, BB*HH), 256, ATTN_SMEM>>>(kh, vh, out_w);

    gemm_h<<<gg, 256, GEMM_SMEM>>>(apreh, wt + 3*(size_t)DD*DD, bc, out_attn, nullptr, 0);
}

// round 10
// speedup vs baseline: 1.7526x; 1.0520x over previous
#include <cuda_runtime.h>
#include <cuda_fp16.h>
#include <cstdint>
#include <math.h>

#define BB 2
#define SS 2048
#define DD 1024
#define HH 16
#define HD 64
#define MM (BB*SS)

// ---------------- scratch ---------------------------------------------------
__device__ __half g_hsh[MM*DD];        // hs fp16 [m][k]
__device__ __half g_wt[4*DD*DD];       // W^T fp16 [n][k] for q,k,v,c
__device__ __half g_qh[BB*HH*SS*HD];   // q fp16 split-head
__device__ __half g_kh[BB*HH*SS*HD];   // k fp16 split-head
__device__ __half g_vh[BB*HH*SS*HD];   // v fp16 split-head
__device__ __half g_apreh[MM*DD];      // attention out pre-c_proj fp16

// ---------------- helpers ---------------------------------------------------
__device__ __forceinline__ void mma_f16(float* d, const uint32_t* a,
                                        const uint32_t* b) {
    asm volatile("mma.sync.aligned.m16n8k16.row.col.f32.f16.f16.f32 "
        "{%0,%1,%2,%3}, {%4,%5,%6,%7}, {%8,%9}, {%0,%1,%2,%3};"
        : "+f"(d[0]), "+f"(d[1]), "+f"(d[2]), "+f"(d[3])
        : "r"(a[0]), "r"(a[1]), "r"(a[2]), "r"(a[3]), "r"(b[0]), "r"(b[1]));
}
__device__ __forceinline__ void ldsm2t(uint32_t& r0, uint32_t& r1, uint32_t sa) {
    asm volatile("ldmatrix.sync.aligned.m8n8.x2.trans.shared.b16 {%0,%1}, [%2];"
                 : "=r"(r0), "=r"(r1) : "r"(sa));
}
__device__ __forceinline__ void cp16(uint32_t s, const void* g) {
    asm volatile("cp.async.cg.shared.global [%0], [%1], 16;"
                 :: "r"(s), "l"(g) : "memory");
}
#define CP_COMMIT() asm volatile("cp.async.commit_group;" ::: "memory")
#define CP_WAIT(n)  asm volatile("cp.async.wait_group %0;" :: "n"(n) : "memory")
__device__ __forceinline__ uint32_t pack_h2(float a, float b) {
    __half2 h = __floats2half2_rn(a, b);
    return *(uint32_t*)&h;
}

// ---------------------------------------------------------------------------
// conversions
// ---------------------------------------------------------------------------
__global__ __launch_bounds__(256) void conv_h(const float* __restrict__ x,
                                              __half* __restrict__ y)
{
    int i = blockIdx.x * 256 + threadIdx.x;
    float4 v = ((const float4*)x)[i];
    ((uint2*)y)[i] = make_uint2(pack_h2(v.x, v.y), pack_h2(v.z, v.w));
}

__global__ __launch_bounds__(256) void tconv4_h(const float* __restrict__ w0,
                                                const float* __restrict__ w1,
                                                const float* __restrict__ w2,
                                                const float* __restrict__ w3,
                                                __half* __restrict__ WtBase)
{
    __shared__ float tile[32][33];
    int z = blockIdx.z;
    const float* W = (z == 0) ? w0 : (z == 1) ? w1 : (z == 2) ? w2 : w3;
    __half* Wt = WtBase + (size_t)z * DD * DD;
    int tx = threadIdx.x & 31, ty = threadIdx.x >> 5;
    int k0 = blockIdx.y << 5, n0 = blockIdx.x << 5;
    #pragma unroll
    for (int i = 0; i < 4; i++)
        tile[ty + 8*i][tx] = W[(size_t)(k0 + ty + 8*i)*DD + n0 + tx];
    __syncthreads();
    #pragma unroll
    for (int i = 0; i < 4; i++)
        Wt[(size_t)(n0 + ty + 8*i)*DD + k0 + tx] = __float2half(tile[tx][ty + 8*i]);
}

// ---------------------------------------------------------------------------
// fp16 GEMM mainloop+epilogue as a device function.
// Block 128x128, 8 warps (2Mx4N), K-chunk 32, 3-stage cp.async.
// ---------------------------------------------------------------------------
#define GS_T (128*40)
#define GEMM_SMEM (3*2*GS_T*2)

__device__ __forceinline__ void gemm_body(const __half* __restrict__ A,
                                          const __half* __restrict__ Wt,
                                          const float* __restrict__ bias,
                                          float* __restrict__ outf32,
                                          __half* __restrict__ outh,
                                          int split, int m0, int n0)
{
    extern __shared__ __half hsm[];
    __half* As = hsm;
    __half* Bs = hsm + 3*GS_T;
    int t = threadIdx.x;
    int wid = t >> 5, lane = t & 31;
    int g = lane >> 2, c = lane & 3;
    int warpM = wid >> 2, warpN = wid & 3;

    float acc[4][4][4];
    #pragma unroll
    for (int mi = 0; mi < 4; mi++)
        #pragma unroll
        for (int ni = 0; ni < 4; ni++)
            #pragma unroll
            for (int r = 0; r < 4; r++) acc[mi][ni][r] = 0.0f;

    int lr = t >> 2, lseg = t & 3;
    const __half* Abase = A  + (size_t)(m0 + lr)*DD + lseg*8;
    const __half* Bbase = Wt + (size_t)(n0 + lr)*DD + lseg*8;
    uint32_t sA = (uint32_t)__cvta_generic_to_shared(&As[lr*40 + lseg*8]);
    uint32_t sB = (uint32_t)__cvta_generic_to_shared(&Bs[lr*40 + lseg*8]);

    #define G_ISSUE(k0c, st) do {                                             \
        cp16(sA + (st)*(GS_T*2),             Abase + (k0c));                  \
        cp16(sA + (st)*(GS_T*2) + 64*40*2,   Abase + (size_t)64*DD + (k0c));  \
        cp16(sB + (st)*(GS_T*2),             Bbase + (k0c));                  \
        cp16(sB + (st)*(GS_T*2) + 64*40*2,   Bbase + (size_t)64*DD + (k0c));  \
        CP_COMMIT(); } while (0)

    G_ISSUE(0, 0);
    G_ISSUE(32, 1);

    for (int cc = 0; cc < 32; cc++) {
        if (cc < 31) CP_WAIT(1); else CP_WAIT(0);
        __syncthreads();
        if (cc + 2 < 32) G_ISSUE((cc+2)*32, (cc+2)%3);

        const __half* Ac = As + (cc%3)*GS_T;
        const __half* Bc = Bs + (cc%3)*GS_T;
        #pragma unroll
        for (int ks = 0; ks < 2; ks++) {
            uint32_t af[4][4], bf[4][2];
            int kc = ks*16 + 2*c;
            #pragma unroll
            for (int mi = 0; mi < 4; mi++) {
                int rb = warpM*64 + mi*16;
                af[mi][0] = *(const uint32_t*)&Ac[(rb+g  )*40 + kc    ];
                af[mi][1] = *(const uint32_t*)&Ac[(rb+g+8)*40 + kc    ];
                af[mi][2] = *(const uint32_t*)&Ac[(rb+g  )*40 + kc + 8];
                af[mi][3] = *(const uint32_t*)&Ac[(rb+g+8)*40 + kc + 8];
            }
            #pragma unroll
            for (int ni = 0; ni < 4; ni++) {
                int nb = warpN*32 + ni*8 + g;
                bf[ni][0] = *(const uint32_t*)&Bc[nb*40 + kc    ];
                bf[ni][1] = *(const uint32_t*)&Bc[nb*40 + kc + 8];
            }
            #pragma unroll
            for (int mi = 0; mi < 4; mi++)
                #pragma unroll
                for (int ni = 0; ni < 4; ni++)
                    mma_f16(acc[mi][ni], af[mi], bf[ni]);
        }
    }

    #pragma unroll
    for (int mi = 0; mi < 4; mi++) {
        int row0 = m0 + warpM*64 + mi*16 + g;
        int b_ = row0 >> 11, s0 = row0 & 2047;
        #pragma unroll
        for (int ni = 0; ni < 4; ni++) {
            int col = n0 + warpN*32 + ni*8 + 2*c;
            float b0 = bias[col], b1 = bias[col+1];
            float2 v0 = make_float2(acc[mi][ni][0] + b0, acc[mi][ni][1] + b1);
            float2 v1 = make_float2(acc[mi][ni][2] + b0, acc[mi][ni][3] + b1);
            int h = col >> 6, ho = col & 63;
            if (outf32) {
                if (split) {
                    *(float2*)&outf32[((size_t)(b_*HH + h)*SS + s0)*HD + ho] = v0;
                    *(float2*)&outf32[((size_t)(b_*HH + h)*SS + s0 + 8)*HD + ho] = v1;
                } else {
                    *(float2*)&outf32[(size_t)row0*DD + col] = v0;
                    *(float2*)&outf32[(size_t)(row0+8)*DD + col] = v1;
                }
            }
            if (outh) {
                *(uint32_t*)&outh[((size_t)(b_*HH + h)*SS + s0)*HD + ho] =
                    pack_h2(v0.x, v0.y);
                *(uint32_t*)&outh[((size_t)(b_*HH + h)*SS + s0 + 8)*HD + ho] =
                    pack_h2(v1.x, v1.y);
            }
        }
    }
}

// merged QKV: blockIdx.z selects projection
__global__ __launch_bounds__(256, 2) void gemm_qkv(const __half* __restrict__ A,
                                                   const __half* __restrict__ wt,
                                                   const float* __restrict__ bq,
                                                   const float* __restrict__ bk,
                                                   const float* __restrict__ bv,
                                                   float* __restrict__ out_k,
                                                   float* __restrict__ out_v,
                                                   __half* __restrict__ qh,
                                                   __half* __restrict__ kh,
                                                   __half* __restrict__ vh)
{
    int z = blockIdx.z;
    const __half* Wt = wt + (size_t)z * DD * DD;
    const float* bias = (z == 0) ? bq : (z == 1) ? bk : bv;
    float* of  = (z == 0) ? nullptr : (z == 1) ? out_k : out_v;
    __half* oh = (z == 0) ? qh : (z == 1) ? kh : vh;
    gemm_body(A, Wt, bias, of, oh, 1, blockIdx.y << 7, blockIdx.x << 7);
}

__global__ __launch_bounds__(256, 2) void gemm_c(const __half* __restrict__ A,
                                                 const __half* __restrict__ Wt,
                                                 const float* __restrict__ bias,
                                                 float* __restrict__ outf32)
{
    gemm_body(A, Wt, bias, outf32, nullptr, 0, blockIdx.y << 7, blockIdx.x << 7);
}

// ---------------------------------------------------------------------------
// Fused attention: phase 1 computes row-sum denominators (QK + exp, no
// stores); phase 2 recomputes S, writes normalized attnw + zero triangle,
// PV -> fp16 g_apreh. One CTA = 64 q-rows of one (b,h); heavy tiles first.
// ---------------------------------------------------------------------------
#define AT_T (64*72)
#define FATTN_SMEM (6*AT_T*2)

__global__ __launch_bounds__(256, 2) void fattn(const __half* __restrict__ kin,
                                                const __half* __restrict__ vin,
                                                float* __restrict__ attnw)
{
    extern __shared__ __half hsm[];
    __half* Qs = hsm;                      // 64x72
    __half* Ks = hsm + AT_T;               // [2][64x72]
    __half* Vs = hsm + 3*AT_T;             // [2][64x72]
    __half* Ps = hsm + 5*AT_T;             // 64x72 (+ float scratch)

    int bh = blockIdx.y;
    int qtile = gridDim.x - 1 - blockIdx.x;
    int q0 = qtile << 6;
    int t = threadIdx.x;
    int wid = t >> 5, lane = t & 31;
    int g = lane >> 2, c = lane & 3;
    int warpM = wid >> 2, warpN = wid & 3;

    const __half* qb = g_qh + (size_t)bh * SS * HD;
    const __half* kb = kin  + (size_t)bh * SS * HD;
    const __half* vb = vin  + (size_t)bh * SS * HD;
    float*        wb = attnw + (size_t)bh * SS * SS;

    // zero-fill upper triangle strip (overlaps with compute)
    {
        float4 z = make_float4(0.f, 0.f, 0.f, 0.f);
        int zr = q0 + (t >> 2);
        for (int col = q0 + 64 + (t & 3)*4; col < SS; col += 16)
            *(float4*)&wb[(size_t)zr*SS + col] = z;
    }

    int lr = t >> 3, lseg = t & 7;
    uint32_t sQ = (uint32_t)__cvta_generic_to_shared(&Qs[lr*72 + lseg*8]);
    uint32_t sK = (uint32_t)__cvta_generic_to_shared(&Ks[lr*72 + lseg*8]);
    uint32_t sV = (uint32_t)__cvta_generic_to_shared(&Vs[lr*72 + lseg*8]);

    cp16(sQ,           &qb[(size_t)(q0 + lr)*HD + lseg*8]);
    cp16(sQ + 32*72*2, &qb[(size_t)(q0 + lr + 32)*HD + lseg*8]);

    #define K_ISSUE(kpos0, st) do {                                           \
        cp16(sK + (st)*(AT_T*2),           &kb[(size_t)((kpos0)+lr)*HD + lseg*8]);     \
        cp16(sK + (st)*(AT_T*2) + 32*72*2, &kb[(size_t)((kpos0)+lr+32)*HD + lseg*8]);  \
        CP_COMMIT(); } while (0)
    #define KV_ISSUE(kpos0, st) do {                                          \
        cp16(sK + (st)*(AT_T*2),           &kb[(size_t)((kpos0)+lr)*HD + lseg*8]);     \
        cp16(sK + (st)*(AT_T*2) + 32*72*2, &kb[(size_t)((kpos0)+lr+32)*HD + lseg*8]);  \
        cp16(sV + (st)*(AT_T*2),           &vb[(size_t)((kpos0)+lr)*HD + lseg*8]);     \
        cp16(sV + (st)*(AT_T*2) + 32*72*2, &vb[(size_t)((kpos0)+lr+32)*HD + lseg*8]);  \
        CP_COMMIT(); } while (0)

    int nkb = qtile + 1;

    // ---------------- phase 1: denominators ----------------
    float psum[2][2] = {{0.f,0.f},{0.f,0.f}};
    K_ISSUE(0, 0);

    for (int kb2 = 0; kb2 < nkb; kb2++) {
        CP_WAIT(0);
        __syncthreads();
        if (kb2 + 1 < nkb) K_ISSUE((kb2+1) << 6, (kb2+1) & 1);
        const __half* Kc = Ks + (kb2 & 1)*AT_T;
        int kpos0 = kb2 << 6;

        float S[2][2][4];
        #pragma unroll
        for (int mi = 0; mi < 2; mi++)
            #pragma unroll
            for (int ni = 0; ni < 2; ni++)
                #pragma unroll
                for (int r = 0; r < 4; r++) S[mi][ni][r] = 0.0f;

        #pragma unroll
        for (int ks = 0; ks < 4; ks++) {
            uint32_t af[2][4], bf[2][2];
            int kc = ks*16 + 2*c;
            #pragma unroll
            for (int mi = 0; mi < 2; mi++) {
                int rb = warpM*32 + mi*16;
                af[mi][0] = *(const uint32_t*)&Qs[(rb+g  )*72 + kc    ];
                af[mi][1] = *(const uint32_t*)&Qs[(rb+g+8)*72 + kc    ];
                af[mi][2] = *(const uint32_t*)&Qs[(rb+g  )*72 + kc + 8];
                af[mi][3] = *(const uint32_t*)&Qs[(rb+g+8)*72 + kc + 8];
            }
            #pragma unroll
            for (int ni = 0; ni < 2; ni++) {
                int nb = warpN*16 + ni*8 + g;
                bf[ni][0] = *(const uint32_t*)&Kc[nb*72 + kc    ];
                bf[ni][1] = *(const uint32_t*)&Kc[nb*72 + kc + 8];
            }
            #pragma unroll
            for (int mi = 0; mi < 2; mi++)
                #pragma unroll
                for (int ni = 0; ni < 2; ni++)
                    mma_f16(S[mi][ni], af[mi], bf[ni]);
        }

        #pragma unroll
        for (int mi = 0; mi < 2; mi++) {
            int row0 = q0 + warpM*32 + mi*16 + g;
            #pragma unroll
            for (int ni = 0; ni < 2; ni++) {
                int key = kpos0 + warpN*16 + ni*8 + 2*c;
                float e00 = (key   <= row0  ) ? __expf(S[mi][ni][0]*0.125f) : 0.f;
                float e01 = (key+1 <= row0  ) ? __expf(S[mi][ni][1]*0.125f) : 0.f;
                float e10 = (key   <= row0+8) ? __expf(S[mi][ni][2]*0.125f) : 0.f;
                float e11 = (key+1 <= row0+8) ? __expf(S[mi][ni][3]*0.125f) : 0.f;
                psum[mi][0] += e00 + e01;
                psum[mi][1] += e10 + e11;
            }
        }
    }

    // reduce -> inv in smem (float scratch over Ps)
    float* red = (float*)Ps;
    #pragma unroll
    for (int mi = 0; mi < 2; mi++)
        #pragma unroll
        for (int hh = 0; hh < 2; hh++) {
            float v = psum[mi][hh];
            v += __shfl_xor_sync(0xFFFFFFFF, v, 1);
            v += __shfl_xor_sync(0xFFFFFFFF, v, 2);
            psum[mi][hh] = v;
        }
    __syncthreads();
    if (c == 0) {
        #pragma unroll
        for (int mi = 0; mi < 2; mi++)
            #pragma unroll
            for (int hh = 0; hh < 2; hh++) {
                int lrow = warpM*32 + mi*16 + g + hh*8;
                red[lrow*4 + warpN] = psum[mi][hh];
            }
    }
    __syncthreads();
    if (t < 64) {
        float l = red[t*4] + red[t*4+1] + red[t*4+2] + red[t*4+3];
        red[256 + t] = 1.0f / l;
    }
    __syncthreads();

    float inv[2][2];
    #pragma unroll
    for (int mi = 0; mi < 2; mi++) {
        int lrow = warpM*32 + mi*16 + g;
        inv[mi][0] = red[256 + lrow];
        inv[mi][1] = red[256 + lrow + 8];
    }
    __syncthreads();   // inv read by all before Ps is overwritten in phase 2

    // ---------------- phase 2: weights + PV ----------------
    float O[2][2][4];
    #pragma unroll
    for (int mi = 0; mi < 2; mi++)
        #pragma unroll
        for (int ni = 0; ni < 2; ni++)
            #pragma unroll
            for (int r = 0; r < 4; r++) O[mi][ni][r] = 0.0f;

    KV_ISSUE(0, 0);

    for (int kb2 = 0; kb2 < nkb; kb2++) {
        CP_WAIT(0);
        __syncthreads();
        if (kb2 + 1 < nkb) KV_ISSUE((kb2+1) << 6, (kb2+1) & 1);

        const __half* Kc = Ks + (kb2 & 1)*AT_T;
        const __half* Vc = Vs + (kb2 & 1)*AT_T;
        int kpos0 = kb2 << 6;

        float S[2][2][4];
        #pragma unroll
        for (int mi = 0; mi < 2; mi++)
            #pragma unroll
            for (int ni = 0; ni < 2; ni++)
                #pragma unroll
                for (int r = 0; r < 4; r++) S[mi][ni][r] = 0.0f;

        #pragma unroll
        for (int ks = 0; ks < 4; ks++) {
            uint32_t af[2][4], bf[2][2];
            int kc = ks*16 + 2*c;
            #pragma unroll
            for (int mi = 0; mi < 2; mi++) {
                int rb = warpM*32 + mi*16;
                af[mi][0] = *(const uint32_t*)&Qs[(rb+g  )*72 + kc    ];
                af[mi][1] = *(const uint32_t*)&Qs[(rb+g+8)*72 + kc    ];
                af[mi][2] = *(const uint32_t*)&Qs[(rb+g  )*72 + kc + 8];
                af[mi][3] = *(const uint32_t*)&Qs[(rb+g+8)*72 + kc + 8];
            }
            #pragma unroll
            for (int ni = 0; ni < 2; ni++) {
                int nb = warpN*16 + ni*8 + g;
                bf[ni][0] = *(const uint32_t*)&Kc[nb*72 + kc    ];
                bf[ni][1] = *(const uint32_t*)&Kc[nb*72 + kc + 8];
            }
            #pragma unroll
            for (int mi = 0; mi < 2; mi++)
                #pragma unroll
                for (int ni = 0; ni < 2; ni++)
                    mma_f16(S[mi][ni], af[mi], bf[ni]);
        }

        #pragma unroll
        for (int mi = 0; mi < 2; mi++) {
            int lrow = warpM*32 + mi*16 + g;
            int row0 = q0 + lrow;
            float i0 = inv[mi][0], i1 = inv[mi][1];
            #pragma unroll
            for (int ni = 0; ni < 2; ni++) {
                int lkey = warpN*16 + ni*8 + 2*c;
                int key = kpos0 + lkey;
                float e00 = (key   <= row0  ) ? __expf(S[mi][ni][0]*0.125f)*i0 : 0.f;
                float e01 = (key+1 <= row0  ) ? __expf(S[mi][ni][1]*0.125f)*i0 : 0.f;
                float e10 = (key   <= row0+8) ? __expf(S[mi][ni][2]*0.125f)*i1 : 0.f;
                float e11 = (key+1 <= row0+8) ? __expf(S[mi][ni][3]*0.125f)*i1 : 0.f;
                *(float2*)&wb[(size_t)row0*SS + key]     = make_float2(e00, e01);
                *(float2*)&wb[(size_t)(row0+8)*SS + key] = make_float2(e10, e11);
                *(uint32_t*)&Ps[lrow*72 + lkey]     = pack_h2(e00, e01);
                *(uint32_t*)&Ps[(lrow+8)*72 + lkey] = pack_h2(e10, e11);
            }
        }
        __syncthreads();

        #pragma unroll
        for (int ks = 0; ks < 4; ks++) {
            uint32_t af[2][4], bf[2][2];
            int kc = ks*16 + 2*c;
            #pragma unroll
            for (int mi = 0; mi < 2; mi++) {
                int rb = warpM*32 + mi*16;
                af[mi][0] = *(const uint32_t*)&Ps[(rb+g  )*72 + kc    ];
                af[mi][1] = *(const uint32_t*)&Ps[(rb+g+8)*72 + kc    ];
                af[mi][2] = *(const uint32_t*)&Ps[(rb+g  )*72 + kc + 8];
                af[mi][3] = *(const uint32_t*)&Ps[(rb+g+8)*72 + kc + 8];
            }
            #pragma unroll
            for (int ni = 0; ni < 2; ni++) {
                int n0v = warpN*16 + ni*8;
                uint32_t sa = (uint32_t)__cvta_generic_to_shared(
                    &Vc[(ks*16 + (lane & 15))*72 + n0v]);
                ldsm2t(bf[ni][0], bf[ni][1], sa);
            }
            #pragma unroll
            for (int mi = 0; mi < 2; mi++)
                #pragma unroll
                for (int ni = 0; ni < 2; ni++)
                    mma_f16(O[mi][ni], af[mi], bf[ni]);
        }
    }

    // output -> fp16 g_apreh [B,S,D]
    int b_ = bh >> 4, h = bh & 15;
    #pragma unroll
    for (int mi = 0; mi < 2; mi++) {
        int lrow = warpM*32 + mi*16 + g;
        int s0 = q0 + lrow;
        #pragma unroll
        for (int ni = 0; ni < 2; ni++) {
            int n = warpN*16 + ni*8 + 2*c;
            *(uint32_t*)&g_apreh[((size_t)b_*SS + s0)*DD + h*HD + n] =
                pack_h2(O[mi][ni][0], O[mi][ni][1]);
            *(uint32_t*)&g_apreh[((size_t)b_*SS + s0 + 8)*DD + h*HD + n] =
                pack_h2(O[mi][ni][2], O[mi][ni][3]);
        }
    }
}

// ---------------------------------------------------------------------------
extern "C" void kernel_launch(void* const* d_in, const int* in_sizes, int n_in,
                              void* d_out, int out_size)
{
    const float* hs = (const float*)d_in[0];
    const float* wq = (const float*)d_in[1];
    const float* bq = (const float*)d_in[2];
    const float* wk = (const float*)d_in[3];
    const float* bk = (const float*)d_in[4];
    const float* wv = (const float*)d_in[5];
    const float* bv = (const float*)d_in[6];
    const float* wc = (const float*)d_in[7];
    const float* bc = (const float*)d_in[8];

    float* out      = (float*)d_out;
    float* out_attn = out;                                   // [B,S,D]
    float* out_w    = out + (size_t)BB*SS*DD;                // [B,H,S,S]
    float* out_k    = out_w + (size_t)BB*HH*SS*SS;           // [B,H,S,hd]
    float* out_v    = out_k + (size_t)BB*HH*SS*HD;           // [B,H,S,hd]

    __half *hsh, *wt, *qh, *kh, *vh, *apreh;
    cudaGetSymbolAddress((void**)&hsh,   g_hsh);
    cudaGetSymbolAddress((void**)&wt,    g_wt);
    cudaGetSymbolAddress((void**)&qh,    g_qh);
    cudaGetSymbolAddress((void**)&kh,    g_kh);
    cudaGetSymbolAddress((void**)&vh,    g_vh);
    cudaGetSymbolAddress((void**)&apreh, g_apreh);

    cudaFuncSetAttribute(gemm_qkv,
                         cudaFuncAttributeMaxDynamicSharedMemorySize, GEMM_SMEM);
    cudaFuncSetAttribute(gemm_c,
                         cudaFuncAttributeMaxDynamicSharedMemorySize, GEMM_SMEM);
    cudaFuncSetAttribute(fattn,
                         cudaFuncAttributeMaxDynamicSharedMemorySize, FATTN_SMEM);

    conv_h<<<(MM*DD/4)/256, 256>>>(hs, hsh);
    tconv4_h<<<dim3(DD/32, DD/32, 4), 256>>>(wq, wk, wv, wc, wt);

    gemm_qkv<<<dim3(DD/128, MM/128, 3), 256, GEMM_SMEM>>>(
        hsh, wt, bq, bk, bv, out_k, out_v, qh, kh, vh);

    fattn<<<dim3(SS/64, BB*HH), 256, FATTN_SMEM>>>(kh, vh, out_w);

    gemm_c<<<dim3(DD/128, MM/128), 256, GEMM_SMEM>>>(
        apreh, wt + 3*(size_t)DD*DD, bc, out_attn);
}

// round 11
// speedup vs baseline: 1.8605x; 1.0616x over previous
#include <cuda_runtime.h>
#include <cuda_fp16.h>
#include <cstdint>
#include <math.h>

#define BB 2
#define SS 2048
#define DD 1024
#define HH 16
#define HD 64
#define MM (BB*SS)

// ---------------- scratch ---------------------------------------------------
__device__ __half g_hsh[MM*DD];        // hs fp16 [m][k]
__device__ __half g_wt[4*DD*DD];       // W^T fp16 [n][k] for q,k,v,c
__device__ __half g_qh[BB*HH*SS*HD];   // q fp16 split-head
__device__ __half g_kh[BB*HH*SS*HD];   // k fp16 split-head
__device__ __half g_vh[BB*HH*SS*HD];   // v fp16 split-head
__device__ __half g_apreh[MM*DD];      // attention out pre-c_proj fp16

// ---------------- helpers ---------------------------------------------------
__device__ __forceinline__ void mma_f16(float* d, const uint32_t* a,
                                        const uint32_t* b) {
    asm volatile("mma.sync.aligned.m16n8k16.row.col.f32.f16.f16.f32 "
        "{%0,%1,%2,%3}, {%4,%5,%6,%7}, {%8,%9}, {%0,%1,%2,%3};"
        : "+f"(d[0]), "+f"(d[1]), "+f"(d[2]), "+f"(d[3])
        : "r"(a[0]), "r"(a[1]), "r"(a[2]), "r"(a[3]), "r"(b[0]), "r"(b[1]));
}
__device__ __forceinline__ void ldsm4(uint32_t* r, uint32_t sa) {
    asm volatile("ldmatrix.sync.aligned.m8n8.x4.shared.b16 {%0,%1,%2,%3}, [%4];"
        : "=r"(r[0]), "=r"(r[1]), "=r"(r[2]), "=r"(r[3]) : "r"(sa));
}
__device__ __forceinline__ void ldsm2(uint32_t& r0, uint32_t& r1, uint32_t sa) {
    asm volatile("ldmatrix.sync.aligned.m8n8.x2.shared.b16 {%0,%1}, [%2];"
        : "=r"(r0), "=r"(r1) : "r"(sa));
}
__device__ __forceinline__ void ldsm2t(uint32_t& r0, uint32_t& r1, uint32_t sa) {
    asm volatile("ldmatrix.sync.aligned.m8n8.x2.trans.shared.b16 {%0,%1}, [%2];"
                 : "=r"(r0), "=r"(r1) : "r"(sa));
}
__device__ __forceinline__ void cp16(uint32_t s, const void* g) {
    asm volatile("cp.async.cg.shared.global [%0], [%1], 16;"
                 :: "r"(s), "l"(g) : "memory");
}
#define CP_COMMIT() asm volatile("cp.async.commit_group;" ::: "memory")
#define CP_WAIT(n)  asm volatile("cp.async.wait_group %0;" :: "n"(n) : "memory")
__device__ __forceinline__ uint32_t pack_h2(float a, float b) {
    __half2 h = __floats2half2_rn(a, b);
    return *(uint32_t*)&h;
}
__device__ __forceinline__ uint32_t sptr(const void* p) {
    return (uint32_t)__cvta_generic_to_shared(p);
}

// ---------------------------------------------------------------------------
// conversions
// ---------------------------------------------------------------------------
__global__ __launch_bounds__(256) void conv_h(const float* __restrict__ x,
                                              __half* __restrict__ y)
{
    int i = blockIdx.x * 256 + threadIdx.x;
    float4 v = ((const float4*)x)[i];
    ((uint2*)y)[i] = make_uint2(pack_h2(v.x, v.y), pack_h2(v.z, v.w));
}

__global__ __launch_bounds__(256) void tconv4_h(const float* __restrict__ w0,
                                                const float* __restrict__ w1,
                                                const float* __restrict__ w2,
                                                const float* __restrict__ w3,
                                                __half* __restrict__ WtBase)
{
    __shared__ float tile[32][33];
    int z = blockIdx.z;
    const float* W = (z == 0) ? w0 : (z == 1) ? w1 : (z == 2) ? w2 : w3;
    __half* Wt = WtBase + (size_t)z * DD * DD;
    int tx = threadIdx.x & 31, ty = threadIdx.x >> 5;
    int k0 = blockIdx.y << 5, n0 = blockIdx.x << 5;
    #pragma unroll
    for (int i = 0; i < 4; i++)
        tile[ty + 8*i][tx] = W[(size_t)(k0 + ty + 8*i)*DD + n0 + tx];
    __syncthreads();
    #pragma unroll
    for (int i = 0; i < 4; i++)
        Wt[(size_t)(n0 + ty + 8*i)*DD + k0 + tx] = __float2half(tile[tx][ty + 8*i]);
}

// ---------------------------------------------------------------------------
// fp16 GEMM with ldmatrix fragment loads. Block 128x128, 8 warps (2Mx4N),
// K-chunk 32, 3-stage cp.async.
// ---------------------------------------------------------------------------
#define GS_T (128*40)
#define GEMM_SMEM (3*2*GS_T*2)

__device__ __forceinline__ void gemm_body(const __half* __restrict__ A,
                                          const __half* __restrict__ Wt,
                                          const float* __restrict__ bias,
                                          float* __restrict__ outf32,
                                          __half* __restrict__ outh,
                                          int split, int m0, int n0)
{
    extern __shared__ __half hsm[];
    __half* As = hsm;
    __half* Bs = hsm + 3*GS_T;
    int t = threadIdx.x;
    int wid = t >> 5, lane = t & 31;
    int g = lane >> 2, c = lane & 3;
    int warpM = wid >> 2, warpN = wid & 3;

    float acc[4][4][4];
    #pragma unroll
    for (int mi = 0; mi < 4; mi++)
        #pragma unroll
        for (int ni = 0; ni < 4; ni++)
            #pragma unroll
            for (int r = 0; r < 4; r++) acc[mi][ni][r] = 0.0f;

    int lr = t >> 2, lseg = t & 3;
    const __half* Abase = A  + (size_t)(m0 + lr)*DD + lseg*8;
    const __half* Bbase = Wt + (size_t)(n0 + lr)*DD + lseg*8;
    uint32_t sA = sptr(&As[lr*40 + lseg*8]);
    uint32_t sB = sptr(&Bs[lr*40 + lseg*8]);

    // ldmatrix lane address components
    int l7 = lane & 7;
    int aRow = warpM*64 + l7 + ((lane >> 3) & 1)*8;   // + mi*16
    int aCol = (lane >> 4)*8;                          // + ks*16
    int bRow = warpN*32 + l7;                          // + ni*8
    int bCol = ((lane >> 3) & 1)*8;                    // + ks*16

    #define G_ISSUE(k0c, st) do {                                             \
        cp16(sA + (st)*(GS_T*2),             Abase + (k0c));                  \
        cp16(sA + (st)*(GS_T*2) + 64*40*2,   Abase + (size_t)64*DD + (k0c));  \
        cp16(sB + (st)*(GS_T*2),             Bbase + (k0c));                  \
        cp16(sB + (st)*(GS_T*2) + 64*40*2,   Bbase + (size_t)64*DD + (k0c));  \
        CP_COMMIT(); } while (0)

    G_ISSUE(0, 0);
    G_ISSUE(32, 1);

    for (int cc = 0; cc < 32; cc++) {
        if (cc < 31) CP_WAIT(1); else CP_WAIT(0);
        __syncthreads();
        if (cc + 2 < 32) G_ISSUE((cc+2)*32, (cc+2)%3);

        const __half* Ac = As + (cc%3)*GS_T;
        const __half* Bc = Bs + (cc%3)*GS_T;
        #pragma unroll
        for (int ks = 0; ks < 2; ks++) {
            uint32_t af[4][4], bf[4][2];
            #pragma unroll
            for (int mi = 0; mi < 4; mi++)
                ldsm4(af[mi], sptr(&Ac[(aRow + mi*16)*40 + ks*16 + aCol]));
            #pragma unroll
            for (int ni = 0; ni < 4; ni++)
                ldsm2(bf[ni][0], bf[ni][1],
                      sptr(&Bc[(bRow + ni*8)*40 + ks*16 + bCol]));
            #pragma unroll
            for (int mi = 0; mi < 4; mi++)
                #pragma unroll
                for (int ni = 0; ni < 4; ni++)
                    mma_f16(acc[mi][ni], af[mi], bf[ni]);
        }
    }

    #pragma unroll
    for (int mi = 0; mi < 4; mi++) {
        int row0 = m0 + warpM*64 + mi*16 + g;
        int b_ = row0 >> 11, s0 = row0 & 2047;
        #pragma unroll
        for (int ni = 0; ni < 4; ni++) {
            int col = n0 + warpN*32 + ni*8 + 2*c;
            float b0 = bias[col], b1 = bias[col+1];
            float2 v0 = make_float2(acc[mi][ni][0] + b0, acc[mi][ni][1] + b1);
            float2 v1 = make_float2(acc[mi][ni][2] + b0, acc[mi][ni][3] + b1);
            int h = col >> 6, ho = col & 63;
            if (outf32) {
                if (split) {
                    *(float2*)&outf32[((size_t)(b_*HH + h)*SS + s0)*HD + ho] = v0;
                    *(float2*)&outf32[((size_t)(b_*HH + h)*SS + s0 + 8)*HD + ho] = v1;
                } else {
                    *(float2*)&outf32[(size_t)row0*DD + col] = v0;
                    *(float2*)&outf32[(size_t)(row0+8)*DD + col] = v1;
                }
            }
            if (outh) {
                *(uint32_t*)&outh[((size_t)(b_*HH + h)*SS + s0)*HD + ho] =
                    pack_h2(v0.x, v0.y);
                *(uint32_t*)&outh[((size_t)(b_*HH + h)*SS + s0 + 8)*HD + ho] =
                    pack_h2(v1.x, v1.y);
            }
        }
    }
}

__global__ __launch_bounds__(256, 2) void gemm_qkv(const __half* __restrict__ A,
                                                   const __half* __restrict__ wt,
                                                   const float* __restrict__ bq,
                                                   const float* __restrict__ bk,
                                                   const float* __restrict__ bv,
                                                   float* __restrict__ out_k,
                                                   float* __restrict__ out_v,
                                                   __half* __restrict__ qh,
                                                   __half* __restrict__ kh,
                                                   __half* __restrict__ vh)
{
    int z = blockIdx.z;
    const __half* Wt = wt + (size_t)z * DD * DD;
    const float* bias = (z == 0) ? bq : (z == 1) ? bk : bv;
    float* of  = (z == 0) ? nullptr : (z == 1) ? out_k : out_v;
    __half* oh = (z == 0) ? qh : (z == 1) ? kh : vh;
    gemm_body(A, Wt, bias, of, oh, 1, blockIdx.y << 7, blockIdx.x << 7);
}

__global__ __launch_bounds__(256, 2) void gemm_c(const __half* __restrict__ A,
                                                 const __half* __restrict__ Wt,
                                                 const float* __restrict__ bias,
                                                 float* __restrict__ outf32)
{
    gemm_body(A, Wt, bias, outf32, nullptr, 0, blockIdx.y << 7, blockIdx.x << 7);
}

// ---------------------------------------------------------------------------
// Fused attention: phase 1 row-sum denominators; phase 2 normalized attnw
// (norm fused into exp argument) + PV. ldmatrix fragment loads throughout.
// ---------------------------------------------------------------------------
#define AT_T (64*72)
#define FATTN_SMEM (6*AT_T*2)

__global__ __launch_bounds__(256, 3) void fattn(const __half* __restrict__ kin,
                                                const __half* __restrict__ vin,
                                                float* __restrict__ attnw)
{
    extern __shared__ __half hsm[];
    __half* Qs = hsm;                      // 64x72
    __half* Ks = hsm + AT_T;               // [2][64x72]
    __half* Vs = hsm + 3*AT_T;             // [2][64x72]
    __half* Ps = hsm + 5*AT_T;             // 64x72 (+ float scratch)

    int bh = blockIdx.y;
    int qtile = gridDim.x - 1 - blockIdx.x;
    int q0 = qtile << 6;
    int t = threadIdx.x;
    int wid = t >> 5, lane = t & 31;
    int g = lane >> 2, c = lane & 3;
    int warpM = wid >> 2, warpN = wid & 3;

    const __half* qb = g_qh + (size_t)bh * SS * HD;
    const __half* kb = kin  + (size_t)bh * SS * HD;
    const __half* vb = vin  + (size_t)bh * SS * HD;
    float*        wb = attnw + (size_t)bh * SS * SS;

    // zero-fill upper triangle strip (overlaps with compute)
    {
        float4 z = make_float4(0.f, 0.f, 0.f, 0.f);
        int zr = q0 + (t >> 2);
        for (int col = q0 + 64 + (t & 3)*4; col < SS; col += 16)
            *(float4*)&wb[(size_t)zr*SS + col] = z;
    }

    int lr = t >> 3, lseg = t & 7;
    uint32_t sQ = sptr(&Qs[lr*72 + lseg*8]);
    uint32_t sK = sptr(&Ks[lr*72 + lseg*8]);
    uint32_t sV = sptr(&Vs[lr*72 + lseg*8]);

    cp16(sQ,           &qb[(size_t)(q0 + lr)*HD + lseg*8]);
    cp16(sQ + 32*72*2, &qb[(size_t)(q0 + lr + 32)*HD + lseg*8]);

    #define K_ISSUE(kpos0, st) do {                                           \
        cp16(sK + (st)*(AT_T*2),           &kb[(size_t)((kpos0)+lr)*HD + lseg*8]);     \
        cp16(sK + (st)*(AT_T*2) + 32*72*2, &kb[(size_t)((kpos0)+lr+32)*HD + lseg*8]);  \
        CP_COMMIT(); } while (0)
    #define KV_ISSUE(kpos0, st) do {                                          \
        cp16(sK + (st)*(AT_T*2),           &kb[(size_t)((kpos0)+lr)*HD + lseg*8]);     \
        cp16(sK + (st)*(AT_T*2) + 32*72*2, &kb[(size_t)((kpos0)+lr+32)*HD + lseg*8]);  \
        cp16(sV + (st)*(AT_T*2),           &vb[(size_t)((kpos0)+lr)*HD + lseg*8]);     \
        cp16(sV + (st)*(AT_T*2) + 32*72*2, &vb[(size_t)((kpos0)+lr+32)*HD + lseg*8]);  \
        CP_COMMIT(); } while (0)

    // ldmatrix lane address components (strides in halves: 72)
    int l7 = lane & 7;
    int aRow = warpM*32 + l7 + ((lane >> 3) & 1)*8;    // + mi*16 (Q / Ps rows)
    int aCol = (lane >> 4)*8;                           // + ks*16
    int bRow = warpN*16 + l7;                           // + ni*8 (K rows)
    int bCol = ((lane >> 3) & 1)*8;                     // + ks*16

    int nkb = qtile + 1;

    // ---------------- phase 1: denominators ----------------
    float psum[2][2] = {{0.f,0.f},{0.f,0.f}};
    K_ISSUE(0, 0);

    for (int kb2 = 0; kb2 < nkb; kb2++) {
        CP_WAIT(0);
        __syncthreads();
        if (kb2 + 1 < nkb) K_ISSUE((kb2+1) << 6, (kb2+1) & 1);
        const __half* Kc = Ks + (kb2 & 1)*AT_T;
        int kpos0 = kb2 << 6;

        float S[2][2][4];
        #pragma unroll
        for (int mi = 0; mi < 2; mi++)
            #pragma unroll
            for (int ni = 0; ni < 2; ni++)
                #pragma unroll
                for (int r = 0; r < 4; r++) S[mi][ni][r] = 0.0f;

        #pragma unroll
        for (int ks = 0; ks < 4; ks++) {
            uint32_t af[2][4], bf[2][2];
            #pragma unroll
            for (int mi = 0; mi < 2; mi++)
                ldsm4(af[mi], sptr(&Qs[(aRow + mi*16)*72 + ks*16 + aCol]));
            #pragma unroll
            for (int ni = 0; ni < 2; ni++)
                ldsm2(bf[ni][0], bf[ni][1],
                      sptr(&Kc[(bRow + ni*8)*72 + ks*16 + bCol]));
            #pragma unroll
            for (int mi = 0; mi < 2; mi++)
                #pragma unroll
                for (int ni = 0; ni < 2; ni++)
                    mma_f16(S[mi][ni], af[mi], bf[ni]);
        }

        #pragma unroll
        for (int mi = 0; mi < 2; mi++) {
            int row0 = q0 + warpM*32 + mi*16 + g;
            #pragma unroll
            for (int ni = 0; ni < 2; ni++) {
                int key = kpos0 + warpN*16 + ni*8 + 2*c;
                float e00 = (key   <= row0  ) ? __expf(S[mi][ni][0]*0.125f) : 0.f;
                float e01 = (key+1 <= row0  ) ? __expf(S[mi][ni][1]*0.125f) : 0.f;
                float e10 = (key   <= row0+8) ? __expf(S[mi][ni][2]*0.125f) : 0.f;
                float e11 = (key+1 <= row0+8) ? __expf(S[mi][ni][3]*0.125f) : 0.f;
                psum[mi][0] += e00 + e01;
                psum[mi][1] += e10 + e11;
            }
        }
    }

    // reduce -> inv in smem (float scratch over Ps)
    float* red = (float*)Ps;
    #pragma unroll
    for (int mi = 0; mi < 2; mi++)
        #pragma unroll
        for (int hh = 0; hh < 2; hh++) {
            float v = psum[mi][hh];
            v += __shfl_xor_sync(0xFFFFFFFF, v, 1);
            v += __shfl_xor_sync(0xFFFFFFFF, v, 2);
            psum[mi][hh] = v;
        }
    __syncthreads();
    if (c == 0) {
        #pragma unroll
        for (int mi = 0; mi < 2; mi++)
            #pragma unroll
            for (int hh = 0; hh < 2; hh++) {
                int lrow = warpM*32 + mi*16 + g + hh*8;
                red[lrow*4 + warpN] = psum[mi][hh];
            }
    }
    __syncthreads();
    if (t < 64) {
        float l = red[t*4] + red[t*4+1] + red[t*4+2] + red[t*4+3];
        red[256 + t] = 1.0f / l;
    }
    __syncthreads();

    float inv[2][2], lninv[2][2];
    #pragma unroll
    for (int mi = 0; mi < 2; mi++) {
        int lrow = warpM*32 + mi*16 + g;
        inv[mi][0] = red[256 + lrow];
        inv[mi][1] = red[256 + lrow + 8];
        lninv[mi][0] = __logf(inv[mi][0]);
        lninv[mi][1] = __logf(inv[mi][1]);
    }
    __syncthreads();   // inv read by all before Ps is overwritten in phase 2

    // ---------------- phase 2: weights + PV ----------------
    float O[2][2][4];
    #pragma unroll
    for (int mi = 0; mi < 2; mi++)
        #pragma unroll
        for (int ni = 0; ni < 2; ni++)
            #pragma unroll
            for (int r = 0; r < 4; r++) O[mi][ni][r] = 0.0f;

    KV_ISSUE(0, 0);

    for (int kb2 = 0; kb2 < nkb; kb2++) {
        CP_WAIT(0);
        __syncthreads();
        if (kb2 + 1 < nkb) KV_ISSUE((kb2+1) << 6, (kb2+1) & 1);

        const __half* Kc = Ks + (kb2 & 1)*AT_T;
        const __half* Vc = Vs + (kb2 & 1)*AT_T;
        int kpos0 = kb2 << 6;

        float S[2][2][4];
        #pragma unroll
        for (int mi = 0; mi < 2; mi++)
            #pragma unroll
            for (int ni = 0; ni < 2; ni++)
                #pragma unroll
                for (int r = 0; r < 4; r++) S[mi][ni][r] = 0.0f;

        #pragma unroll
        for (int ks = 0; ks < 4; ks++) {
            uint32_t af[2][4], bf[2][2];
            #pragma unroll
            for (int mi = 0; mi < 2; mi++)
                ldsm4(af[mi], sptr(&Qs[(aRow + mi*16)*72 + ks*16 + aCol]));
            #pragma unroll
            for (int ni = 0; ni < 2; ni++)
                ldsm2(bf[ni][0], bf[ni][1],
                      sptr(&Kc[(bRow + ni*8)*72 + ks*16 + bCol]));
            #pragma unroll
            for (int mi = 0; mi < 2; mi++)
                #pragma unroll
                for (int ni = 0; ni < 2; ni++)
                    mma_f16(S[mi][ni], af[mi], bf[ni]);
        }

        // exp(S/8 + ln(inv)) = normalized weight; fp32 -> attnw, fp16 -> Ps
        #pragma unroll
        for (int mi = 0; mi < 2; mi++) {
            int lrow = warpM*32 + mi*16 + g;
            int row0 = q0 + lrow;
            float L0 = lninv[mi][0], L1 = lninv[mi][1];
            #pragma unroll
            for (int ni = 0; ni < 2; ni++) {
                int lkey = warpN*16 + ni*8 + 2*c;
                int key = kpos0 + lkey;
                float e00 = (key   <= row0  ) ? __expf(fmaf(S[mi][ni][0], 0.125f, L0)) : 0.f;
                float e01 = (key+1 <= row0  ) ? __expf(fmaf(S[mi][ni][1], 0.125f, L0)) : 0.f;
                float e10 = (key   <= row0+8) ? __expf(fmaf(S[mi][ni][2], 0.125f, L1)) : 0.f;
                float e11 = (key+1 <= row0+8) ? __expf(fmaf(S[mi][ni][3], 0.125f, L1)) : 0.f;
                *(float2*)&wb[(size_t)row0*SS + key]     = make_float2(e00, e01);
                *(float2*)&wb[(size_t)(row0+8)*SS + key] = make_float2(e10, e11);
                *(uint32_t*)&Ps[lrow*72 + lkey]     = pack_h2(e00, e01);
                *(uint32_t*)&Ps[(lrow+8)*72 + lkey] = pack_h2(e10, e11);
            }
        }
        __syncthreads();

        // O += P V
        #pragma unroll
        for (int ks = 0; ks < 4; ks++) {
            uint32_t af[2][4], bf[2][2];
            #pragma unroll
            for (int mi = 0; mi < 2; mi++)
                ldsm4(af[mi], sptr(&Ps[(aRow + mi*16)*72 + ks*16 + aCol]));
            #pragma unroll
            for (int ni = 0; ni < 2; ni++) {
                int n0v = warpN*16 + ni*8;
                ldsm2t(bf[ni][0], bf[ni][1],
                       sptr(&Vc[(ks*16 + (lane & 15))*72 + n0v]));
            }
            #pragma unroll
            for (int mi = 0; mi < 2; mi++)
                #pragma unroll
                for (int ni = 0; ni < 2; ni++)
                    mma_f16(O[mi][ni], af[mi], bf[ni]);
        }
    }

    // output -> fp16 g_apreh [B,S,D]
    int b_ = bh >> 4, h = bh & 15;
    #pragma unroll
    for (int mi = 0; mi < 2; mi++) {
        int lrow = warpM*32 + mi*16 + g;
        int s0 = q0 + lrow;
        #pragma unroll
        for (int ni = 0; ni < 2; ni++) {
            int n = warpN*16 + ni*8 + 2*c;
            *(uint32_t*)&g_apreh[((size_t)b_*SS + s0)*DD + h*HD + n] =
                pack_h2(O[mi][ni][0], O[mi][ni][1]);
            *(uint32_t*)&g_apreh[((size_t)b_*SS + s0 + 8)*DD + h*HD + n] =
                pack_h2(O[mi][ni][2], O[mi][ni][3]);
        }
    }
}

// ---------------------------------------------------------------------------
extern "C" void kernel_launch(void* const* d_in, const int* in_sizes, int n_in,
                              void* d_out, int out_size)
{
    const float* hs = (const float*)d_in[0];
    const float* wq = (const float*)d_in[1];
    const float* bq = (const float*)d_in[2];
    const float* wk = (const float*)d_in[3];
    const float* bk = (const float*)d_in[4];
    const float* wv = (const float*)d_in[5];
    const float* bv = (const float*)d_in[6];
    const float* wc = (const float*)d_in[7];
    const float* bc = (const float*)d_in[8];

    float* out      = (float*)d_out;
    float* out_attn = out;                                   // [B,S,D]
    float* out_w    = out + (size_t)BB*SS*DD;                // [B,H,S,S]
    float* out_k    = out_w + (size_t)BB*HH*SS*SS;           // [B,H,S,hd]
    float* out_v    = out_k + (size_t)BB*HH*SS*HD;           // [B,H,S,hd]

    __half *hsh, *wt, *qh, *kh, *vh, *apreh;
    cudaGetSymbolAddress((void**)&hsh,   g_hsh);
    cudaGetSymbolAddress((void**)&wt,    g_wt);
    cudaGetSymbolAddress((void**)&qh,    g_qh);
    cudaGetSymbolAddress((void**)&kh,    g_kh);
    cudaGetSymbolAddress((void**)&vh,    g_vh);
    cudaGetSymbolAddress((void**)&apreh, g_apreh);

    cudaFuncSetAttribute(gemm_qkv,
                         cudaFuncAttributeMaxDynamicSharedMemorySize, GEMM_SMEM);
    cudaFuncSetAttribute(gemm_c,
                         cudaFuncAttributeMaxDynamicSharedMemorySize, GEMM_SMEM);
    cudaFuncSetAttribute(fattn,
                         cudaFuncAttributeMaxDynamicSharedMemorySize, FATTN_SMEM);

    conv_h<<<(MM*DD/4)/256, 256>>>(hs, hsh);
    tconv4_h<<<dim3(DD/32, DD/32, 4), 256>>>(wq, wk, wv, wc, wt);

    gemm_qkv<<<dim3(DD/128, MM/128, 3), 256, GEMM_SMEM>>>(
        hsh, wt, bq, bk, bv, out_k, out_v, qh, kh, vh);

    fattn<<<dim3(SS/64, BB*HH), 256, FATTN_SMEM>>>(kh, vh, out_w);

    gemm_c<<<dim3(DD/128, MM/128), 256, GEMM_SMEM>>>(
        apreh, wt + 3*(size_t)DD*DD, bc, out_attn);
}

// round 12
// speedup vs baseline: 1.8806x; 1.0108x over previous
#include <cuda_runtime.h>
#include <cuda_fp16.h>
#include <cstdint>
#include <math.h>

#define BB 2
#define SS 2048
#define DD 1024
#define HH 16
#define HD 64
#define MM (BB*SS)

// q pre-scale: 1/8 (attention scale) * log2(e)  -> softmax uses ex2
#define QSCL 0.18033688011112042f

// ---------------- scratch ---------------------------------------------------
__device__ __half g_hsh[MM*DD];        // hs fp16 [m][k]
__device__ __half g_wt[4*DD*DD];       // W^T fp16 [n][k] for q,k,v,c
__device__ __half g_qh[BB*HH*SS*HD];   // q fp16 split-head (pre-scaled by QSCL)
__device__ __half g_kh[BB*HH*SS*HD];   // k fp16 split-head
__device__ __half g_vh[BB*HH*SS*HD];   // v fp16 split-head
__device__ __half g_apreh[MM*DD];      // attention out pre-c_proj fp16

// ---------------- helpers ---------------------------------------------------
__device__ __forceinline__ void mma_f16(float* d, const uint32_t* a,
                                        const uint32_t* b) {
    asm volatile("mma.sync.aligned.m16n8k16.row.col.f32.f16.f16.f32 "
        "{%0,%1,%2,%3}, {%4,%5,%6,%7}, {%8,%9}, {%0,%1,%2,%3};"
        : "+f"(d[0]), "+f"(d[1]), "+f"(d[2]), "+f"(d[3])
        : "r"(a[0]), "r"(a[1]), "r"(a[2]), "r"(a[3]), "r"(b[0]), "r"(b[1]));
}
__device__ __forceinline__ void ldsm4(uint32_t* r, uint32_t sa) {
    asm volatile("ldmatrix.sync.aligned.m8n8.x4.shared.b16 {%0,%1,%2,%3}, [%4];"
        : "=r"(r[0]), "=r"(r[1]), "=r"(r[2]), "=r"(r[3]) : "r"(sa));
}
__device__ __forceinline__ void ldsm2(uint32_t& r0, uint32_t& r1, uint32_t sa) {
    asm volatile("ldmatrix.sync.aligned.m8n8.x2.shared.b16 {%0,%1}, [%2];"
        : "=r"(r0), "=r"(r1) : "r"(sa));
}
__device__ __forceinline__ void ldsm2t(uint32_t& r0, uint32_t& r1, uint32_t sa) {
    asm volatile("ldmatrix.sync.aligned.m8n8.x2.trans.shared.b16 {%0,%1}, [%2];"
                 : "=r"(r0), "=r"(r1) : "r"(sa));
}
__device__ __forceinline__ void cp16(uint32_t s, const void* g) {
    asm volatile("cp.async.cg.shared.global [%0], [%1], 16;"
                 :: "r"(s), "l"(g) : "memory");
}
#define CP_COMMIT() asm volatile("cp.async.commit_group;" ::: "memory")
#define CP_WAIT(n)  asm volatile("cp.async.wait_group %0;" :: "n"(n) : "memory")
__device__ __forceinline__ uint32_t pack_h2(float a, float b) {
    __half2 h = __floats2half2_rn(a, b);
    return *(uint32_t*)&h;
}
__device__ __forceinline__ uint32_t sptr(const void* p) {
    return (uint32_t)__cvta_generic_to_shared(p);
}
__device__ __forceinline__ float ex2f(float x) {
    float r;
    asm("ex2.approx.f32 %0, %1;" : "=f"(r) : "f"(x));
    return r;
}

// ---------------------------------------------------------------------------
// conversions
// ---------------------------------------------------------------------------
__global__ __launch_bounds__(256) void conv_h(const float* __restrict__ x,
                                              __half* __restrict__ y)
{
    int i = blockIdx.x * 256 + threadIdx.x;
    float4 v = ((const float4*)x)[i];
    ((uint2*)y)[i] = make_uint2(pack_h2(v.x, v.y), pack_h2(v.z, v.w));
}

__global__ __launch_bounds__(256) void tconv4_h(const float* __restrict__ w0,
                                                const float* __restrict__ w1,
                                                const float* __restrict__ w2,
                                                const float* __restrict__ w3,
                                                __half* __restrict__ WtBase)
{
    __shared__ float tile[32][33];
    int z = blockIdx.z;
    const float* W = (z == 0) ? w0 : (z == 1) ? w1 : (z == 2) ? w2 : w3;
    __half* Wt = WtBase + (size_t)z * DD * DD;
    int tx = threadIdx.x & 31, ty = threadIdx.x >> 5;
    int k0 = blockIdx.y << 5, n0 = blockIdx.x << 5;
    #pragma unroll
    for (int i = 0; i < 4; i++)
        tile[ty + 8*i][tx] = W[(size_t)(k0 + ty + 8*i)*DD + n0 + tx];
    __syncthreads();
    #pragma unroll
    for (int i = 0; i < 4; i++)
        Wt[(size_t)(n0 + ty + 8*i)*DD + k0 + tx] = __float2half(tile[tx][ty + 8*i]);
}

// ---------------------------------------------------------------------------
// fp16 GEMM (as R11): ldmatrix fragments, 3-stage cp.async, 128x128 tiles.
// 'os' scales the fp16 (outh) output only.
// ---------------------------------------------------------------------------
#define GS_T (128*40)
#define GEMM_SMEM (3*2*GS_T*2)

__device__ __forceinline__ void gemm_body(const __half* __restrict__ A,
                                          const __half* __restrict__ Wt,
                                          const float* __restrict__ bias,
                                          float* __restrict__ outf32,
                                          __half* __restrict__ outh,
                                          int split, int m0, int n0, float os)
{
    extern __shared__ __half hsm[];
    __half* As = hsm;
    __half* Bs = hsm + 3*GS_T;
    int t = threadIdx.x;
    int wid = t >> 5, lane = t & 31;
    int g = lane >> 2, c = lane & 3;
    int warpM = wid >> 2, warpN = wid & 3;

    float acc[4][4][4];
    #pragma unroll
    for (int mi = 0; mi < 4; mi++)
        #pragma unroll
        for (int ni = 0; ni < 4; ni++)
            #pragma unroll
            for (int r = 0; r < 4; r++) acc[mi][ni][r] = 0.0f;

    int lr = t >> 2, lseg = t & 3;
    const __half* Abase = A  + (size_t)(m0 + lr)*DD + lseg*8;
    const __half* Bbase = Wt + (size_t)(n0 + lr)*DD + lseg*8;
    uint32_t sA = sptr(&As[lr*40 + lseg*8]);
    uint32_t sB = sptr(&Bs[lr*40 + lseg*8]);

    int l7 = lane & 7;
    int aRow = warpM*64 + l7 + ((lane >> 3) & 1)*8;
    int aCol = (lane >> 4)*8;
    int bRow = warpN*32 + l7;
    int bCol = ((lane >> 3) & 1)*8;

    #define G_ISSUE(k0c, st) do {                                             \
        cp16(sA + (st)*(GS_T*2),             Abase + (k0c));                  \
        cp16(sA + (st)*(GS_T*2) + 64*40*2,   Abase + (size_t)64*DD + (k0c));  \
        cp16(sB + (st)*(GS_T*2),             Bbase + (k0c));                  \
        cp16(sB + (st)*(GS_T*2) + 64*40*2,   Bbase + (size_t)64*DD + (k0c));  \
        CP_COMMIT(); } while (0)

    G_ISSUE(0, 0);
    G_ISSUE(32, 1);

    for (int cc = 0; cc < 32; cc++) {
        if (cc < 31) CP_WAIT(1); else CP_WAIT(0);
        __syncthreads();
        if (cc + 2 < 32) G_ISSUE((cc+2)*32, (cc+2)%3);

        const __half* Ac = As + (cc%3)*GS_T;
        const __half* Bc = Bs + (cc%3)*GS_T;
        #pragma unroll
        for (int ks = 0; ks < 2; ks++) {
            uint32_t af[4][4], bf[4][2];
            #pragma unroll
            for (int mi = 0; mi < 4; mi++)
                ldsm4(af[mi], sptr(&Ac[(aRow + mi*16)*40 + ks*16 + aCol]));
            #pragma unroll
            for (int ni = 0; ni < 4; ni++)
                ldsm2(bf[ni][0], bf[ni][1],
                      sptr(&Bc[(bRow + ni*8)*40 + ks*16 + bCol]));
            #pragma unroll
            for (int mi = 0; mi < 4; mi++)
                #pragma unroll
                for (int ni = 0; ni < 4; ni++)
                    mma_f16(acc[mi][ni], af[mi], bf[ni]);
        }
    }

    #pragma unroll
    for (int mi = 0; mi < 4; mi++) {
        int row0 = m0 + warpM*64 + mi*16 + g;
        int b_ = row0 >> 11, s0 = row0 & 2047;
        #pragma unroll
        for (int ni = 0; ni < 4; ni++) {
            int col = n0 + warpN*32 + ni*8 + 2*c;
            float b0 = bias[col], b1 = bias[col+1];
            float2 v0 = make_float2(acc[mi][ni][0] + b0, acc[mi][ni][1] + b1);
            float2 v1 = make_float2(acc[mi][ni][2] + b0, acc[mi][ni][3] + b1);
            int h = col >> 6, ho = col & 63;
            if (outf32) {
                if (split) {
                    *(float2*)&outf32[((size_t)(b_*HH + h)*SS + s0)*HD + ho] = v0;
                    *(float2*)&outf32[((size_t)(b_*HH + h)*SS + s0 + 8)*HD + ho] = v1;
                } else {
                    *(float2*)&outf32[(size_t)row0*DD + col] = v0;
                    *(float2*)&outf32[(size_t)(row0+8)*DD + col] = v1;
                }
            }
            if (outh) {
                *(uint32_t*)&outh[((size_t)(b_*HH + h)*SS + s0)*HD + ho] =
                    pack_h2(v0.x*os, v0.y*os);
                *(uint32_t*)&outh[((size_t)(b_*HH + h)*SS + s0 + 8)*HD + ho] =
                    pack_h2(v1.x*os, v1.y*os);
            }
        }
    }
}

__global__ __launch_bounds__(256, 2) void gemm_qkv(const __half* __restrict__ A,
                                                   const __half* __restrict__ wt,
                                                   const float* __restrict__ bq,
                                                   const float* __restrict__ bk,
                                                   const float* __restrict__ bv,
                                                   float* __restrict__ out_k,
                                                   float* __restrict__ out_v,
                                                   __half* __restrict__ qh,
                                                   __half* __restrict__ kh,
                                                   __half* __restrict__ vh)
{
    int z = blockIdx.z;
    const __half* Wt = wt + (size_t)z * DD * DD;
    const float* bias = (z == 0) ? bq : (z == 1) ? bk : bv;
    float* of  = (z == 0) ? nullptr : (z == 1) ? out_k : out_v;
    __half* oh = (z == 0) ? qh : (z == 1) ? kh : vh;
    float os   = (z == 0) ? QSCL : 1.0f;
    gemm_body(A, Wt, bias, of, oh, 1, blockIdx.y << 7, blockIdx.x << 7, os);
}

__global__ __launch_bounds__(256, 2) void gemm_c(const __half* __restrict__ A,
                                                 const __half* __restrict__ Wt,
                                                 const float* __restrict__ bias,
                                                 float* __restrict__ outf32)
{
    gemm_body(A, Wt, bias, outf32, nullptr, 0, blockIdx.y << 7, blockIdx.x << 7, 1.0f);
}

// ---------------------------------------------------------------------------
// Fused attention.
// Phase 1: denominators via 128-key K tiles, Q fragments hoisted to regs.
// Phase 2: normalized attnw + PV with S->A register reuse (no P smem),
//          per-warp key-slice PV partials, cross-warpN reduction at epilogue.
// smem: Q (64x72) + 4 tile slots (phase1: 2 stages x 128 rows;
//       phase2: K[2] + V[2] x 64 rows) = 5*AT_T halves = 46 KB.
// ---------------------------------------------------------------------------
#define AT_T (64*72)
#define FATTN_SMEM (5*AT_T*2)

__global__ __launch_bounds__(256, 2) void fattn(const __half* __restrict__ kin,
                                                const __half* __restrict__ vin,
                                                float* __restrict__ attnw)
{
    extern __shared__ __half hsm[];
    __half* Qs = hsm;                      // 64x72

    int bh = blockIdx.y;
    int qtile = gridDim.x - 1 - blockIdx.x;   // heavy tiles first
    int q0 = qtile << 6;
    int t = threadIdx.x;
    int wid = t >> 5, lane = t & 31;
    int g = lane >> 2, c = lane & 3;
    int warpM = wid >> 2, warpN = wid & 3;

    const __half* qb = g_qh + (size_t)bh * SS * HD;
    const __half* kb = kin  + (size_t)bh * SS * HD;
    const __half* vb = vin  + (size_t)bh * SS * HD;
    float*        wb = attnw + (size_t)bh * SS * SS;

    // zero-fill upper triangle strip (overlaps with compute)
    {
        float4 z = make_float4(0.f, 0.f, 0.f, 0.f);
        int zr = q0 + (t >> 2);
        for (int col = q0 + 64 + (t & 3)*4; col < SS; col += 16)
            *(float4*)&wb[(size_t)zr*SS + col] = z;
    }

    int lr = t >> 3, lseg = t & 7;
    // ldmatrix lane address components
    int l7 = lane & 7;
    int aRow = warpM*32 + l7 + ((lane >> 3) & 1)*8;   // + mi*16
    int aCol = (lane >> 4)*8;                          // + ks*16
    int bRow = warpN*16 + l7;                          // + ni*8
    int bCol = ((lane >> 3) & 1)*8;                    // + ks*16

    // Q load
    uint32_t sQ = sptr(&Qs[lr*72 + lseg*8]);
    cp16(sQ,           &qb[(size_t)(q0 + lr)*HD + lseg*8]);
    cp16(sQ + 32*72*2, &qb[(size_t)(q0 + lr + 32)*HD + lseg*8]);
    CP_COMMIT();

    int nkb = qtile + 1;
    int nkb128 = (nkb + 1) >> 1;

    // phase-1 stage bases (128 rows each): hsm + AT_T, hsm + 3*AT_T
    uint32_t sK1 = sptr(&hsm[AT_T + lr*72 + lseg*8]);
    #define K128_ISSUE(kpos0, st) do {                                        \
        _Pragma("unroll")                                                     \
        for (int i = 0; i < 4; i++)                                           \
            cp16(sK1 + (st)*(2*AT_T*2) + i*(32*72*2),                         \
                 &kb[(size_t)((kpos0) + lr + 32*i)*HD + lseg*8]);             \
        CP_COMMIT(); } while (0)

    K128_ISSUE(0, 0);
    CP_WAIT(0);
    __syncthreads();

    // hoist Q fragments (used by both phases' QK... phase1 only, phase2 reloads)
    uint32_t qf[4][2][4];
    #pragma unroll
    for (int ks = 0; ks < 4; ks++)
        #pragma unroll
        for (int mi = 0; mi < 2; mi++)
            ldsm4(qf[ks][mi], sptr(&Qs[(aRow + mi*16)*72 + ks*16 + aCol]));

    if (nkb128 > 1) K128_ISSUE(128, 1);

    float psum[2][2] = {{0.f,0.f},{0.f,0.f}};

    for (int j = 0; j < nkb128; j++) {
        if (j > 0) {
            CP_WAIT(0);
            __syncthreads();
            if (j + 1 < nkb128) K128_ISSUE((j+1)*128, (j+1) & 1);
        }
        const __half* Kst = hsm + AT_T + (j & 1)*(2*AT_T);

        #pragma unroll
        for (int sb = 0; sb < 2; sb++) {
            if (j*2 + sb >= nkb) break;
            const __half* Kc = Kst + sb*(64*72);
            int kpos0 = (j*2 + sb) << 6;

            float S[2][2][4];
            #pragma unroll
            for (int mi = 0; mi < 2; mi++)
                #pragma unroll
                for (int ni = 0; ni < 2; ni++)
                    #pragma unroll
                    for (int r = 0; r < 4; r++) S[mi][ni][r] = 0.0f;

            #pragma unroll
            for (int ks = 0; ks < 4; ks++) {
                uint32_t bf[2][2];
                #pragma unroll
                for (int ni = 0; ni < 2; ni++)
                    ldsm2(bf[ni][0], bf[ni][1],
                          sptr(&Kc[(bRow + ni*8)*72 + ks*16 + bCol]));
                #pragma unroll
                for (int mi = 0; mi < 2; mi++)
                    #pragma unroll
                    for (int ni = 0; ni < 2; ni++)
                        mma_f16(S[mi][ni], qf[ks][mi], bf[ni]);
            }

            #pragma unroll
            for (int mi = 0; mi < 2; mi++) {
                int row0 = q0 + warpM*32 + mi*16 + g;
                #pragma unroll
                for (int ni = 0; ni < 2; ni++) {
                    int key = kpos0 + warpN*16 + ni*8 + 2*c;
                    float e00 = (key   <= row0  ) ? ex2f(S[mi][ni][0]) : 0.f;
                    float e01 = (key+1 <= row0  ) ? ex2f(S[mi][ni][1]) : 0.f;
                    float e10 = (key   <= row0+8) ? ex2f(S[mi][ni][2]) : 0.f;
                    float e11 = (key+1 <= row0+8) ? ex2f(S[mi][ni][3]) : 0.f;
                    psum[mi][0] += e00 + e01;
                    psum[mi][1] += e10 + e11;
                }
            }
        }
    }
    __syncthreads();

    // reduce -> log2(1/l) per owned row
    float* red = (float*)(hsm + AT_T);
    #pragma unroll
    for (int mi = 0; mi < 2; mi++)
        #pragma unroll
        for (int hh = 0; hh < 2; hh++) {
            float v = psum[mi][hh];
            v += __shfl_xor_sync(0xFFFFFFFF, v, 1);
            v += __shfl_xor_sync(0xFFFFFFFF, v, 2);
            psum[mi][hh] = v;
        }
    if (c == 0) {
        #pragma unroll
        for (int mi = 0; mi < 2; mi++)
            #pragma unroll
            for (int hh = 0; hh < 2; hh++) {
                int lrow = warpM*32 + mi*16 + g + hh*8;
                red[lrow*4 + warpN] = psum[mi][hh];
            }
    }
    __syncthreads();
    if (t < 64) {
        float l = red[t*4] + red[t*4+1] + red[t*4+2] + red[t*4+3];
        red[256 + t] = 1.0f / l;
    }
    __syncthreads();

    float L2i[2][2];
    #pragma unroll
    for (int mi = 0; mi < 2; mi++) {
        int lrow = warpM*32 + mi*16 + g;
        L2i[mi][0] = __log2f(red[256 + lrow]);
        L2i[mi][1] = __log2f(red[256 + lrow + 8]);
    }
    __syncthreads();   // before phase-2 cp.async overwrites red region

    // ---------------- phase 2 ----------------
    // stages: K at hsm + AT_T + st*AT_T ; V at hsm + 3*AT_T + st*AT_T
    uint32_t sK2 = sptr(&hsm[AT_T   + lr*72 + lseg*8]);
    uint32_t sV2 = sptr(&hsm[3*AT_T + lr*72 + lseg*8]);
    #define KV_ISSUE(kpos0, st) do {                                          \
        cp16(sK2 + (st)*(AT_T*2),           &kb[(size_t)((kpos0)+lr)*HD + lseg*8]);    \
        cp16(sK2 + (st)*(AT_T*2) + 32*72*2, &kb[(size_t)((kpos0)+lr+32)*HD + lseg*8]); \
        cp16(sV2 + (st)*(AT_T*2),           &vb[(size_t)((kpos0)+lr)*HD + lseg*8]);    \
        cp16(sV2 + (st)*(AT_T*2) + 32*72*2, &vb[(size_t)((kpos0)+lr+32)*HD + lseg*8]); \
        CP_COMMIT(); } while (0)

    float O[2][8][4];
    #pragma unroll
    for (int mi = 0; mi < 2; mi++)
        #pragma unroll
        for (int ni = 0; ni < 8; ni++)
            #pragma unroll
            for (int r = 0; r < 4; r++) O[mi][ni][r] = 0.0f;

    KV_ISSUE(0, 0);

    for (int kb2 = 0; kb2 < nkb; kb2++) {
        CP_WAIT(0);
        __syncthreads();
        if (kb2 + 1 < nkb) KV_ISSUE((kb2+1) << 6, (kb2+1) & 1);

        const __half* Kc = hsm + AT_T   + (kb2 & 1)*AT_T;
        const __half* Vc = hsm + 3*AT_T + (kb2 & 1)*AT_T;
        int kpos0 = kb2 << 6;

        // QK over hd=64
        float S[2][2][4];
        #pragma unroll
        for (int mi = 0; mi < 2; mi++)
            #pragma unroll
            for (int ni = 0; ni < 2; ni++)
                #pragma unroll
                for (int r = 0; r < 4; r++) S[mi][ni][r] = 0.0f;

        #pragma unroll
        for (int ks = 0; ks < 4; ks++) {
            uint32_t af[2][4], bf[2][2];
            #pragma unroll
            for (int mi = 0; mi < 2; mi++)
                ldsm4(af[mi], sptr(&Qs[(aRow + mi*16)*72 + ks*16 + aCol]));
            #pragma unroll
            for (int ni = 0; ni < 2; ni++)
                ldsm2(bf[ni][0], bf[ni][1],
                      sptr(&Kc[(bRow + ni*8)*72 + ks*16 + bCol]));
            #pragma unroll
            for (int mi = 0; mi < 2; mi++)
                #pragma unroll
                for (int ni = 0; ni < 2; ni++)
                    mma_f16(S[mi][ni], af[mi], bf[ni]);
        }

        // normalized weights: ex2(S + log2(inv)); store attnw; pack A-fragments
        uint32_t ap[2][4];
        #pragma unroll
        for (int mi = 0; mi < 2; mi++) {
            int lrow = warpM*32 + mi*16 + g;
            int row0 = q0 + lrow;
            float L0 = L2i[mi][0], L1 = L2i[mi][1];
            #pragma unroll
            for (int ni = 0; ni < 2; ni++) {
                int key = kpos0 + warpN*16 + ni*8 + 2*c;
                float e00 = (key   <= row0  ) ? ex2f(S[mi][ni][0] + L0) : 0.f;
                float e01 = (key+1 <= row0  ) ? ex2f(S[mi][ni][1] + L0) : 0.f;
                float e10 = (key   <= row0+8) ? ex2f(S[mi][ni][2] + L1) : 0.f;
                float e11 = (key+1 <= row0+8) ? ex2f(S[mi][ni][3] + L1) : 0.f;
                *(float2*)&wb[(size_t)row0*SS + key]     = make_float2(e00, e01);
                *(float2*)&wb[(size_t)(row0+8)*SS + key] = make_float2(e10, e11);
                ap[mi][ni*2    ] = pack_h2(e00, e01);
                ap[mi][ni*2 + 1] = pack_h2(e10, e11);
            }
        }

        // PV: k = this warp's 16-key slice, N = full hd 64; no smem P
        #pragma unroll
        for (int ni = 0; ni < 8; ni++) {
            uint32_t bb[2];
            ldsm2t(bb[0], bb[1],
                   sptr(&Vc[(warpN*16 + (lane & 15))*72 + ni*8]));
            mma_f16(O[0][ni], ap[0], bb);
            mma_f16(O[1][ni], ap[1], bb);
        }
    }

    // epilogue: reduce O across warpN via smem, then write fp16 apre
    __syncthreads();
    float* Osm = (float*)hsm;   // 64 x 65 fp32
    #pragma unroll 1
    for (int wn = 0; wn < 4; wn++) {
        if (warpN == wn) {
            #pragma unroll
            for (int mi = 0; mi < 2; mi++) {
                int rr = warpM*32 + mi*16 + g;
                #pragma unroll
                for (int ni = 0; ni < 8; ni++) {
                    int cc2 = ni*8 + 2*c;
                    if (wn == 0) {
                        Osm[rr*65 + cc2]       = O[mi][ni][0];
                        Osm[rr*65 + cc2 + 1]   = O[mi][ni][1];
                        Osm[(rr+8)*65 + cc2]   = O[mi][ni][2];
                        Osm[(rr+8)*65 + cc2+1] = O[mi][ni][3];
                    } else {
                        Osm[rr*65 + cc2]       += O[mi][ni][0];
                        Osm[rr*65 + cc2 + 1]   += O[mi][ni][1];
                        Osm[(rr+8)*65 + cc2]   += O[mi][ni][2];
                        Osm[(rr+8)*65 + cc2+1] += O[mi][ni][3];
                    }
                }
            }
        }
        __syncthreads();
    }

    {
        int b_ = bh >> 4, h = bh & 15;
        int row = t >> 2, cb = (t & 3) * 16;
        int s0 = q0 + row;
        uint32_t w[8];
        #pragma unroll
        for (int j = 0; j < 8; j++)
            w[j] = pack_h2(Osm[row*65 + cb + 2*j], Osm[row*65 + cb + 2*j + 1]);
        __half* dst = &g_apreh[((size_t)b_*SS + s0)*DD + h*HD + cb];
        *(uint4*)dst       = make_uint4(w[0], w[1], w[2], w[3]);
        *(uint4*)(dst + 8) = make_uint4(w[4], w[5], w[6], w[7]);
    }
}

// ---------------------------------------------------------------------------
extern "C" void kernel_launch(void* const* d_in, const int* in_sizes, int n_in,
                              void* d_out, int out_size)
{
    const float* hs = (const float*)d_in[0];
    const float* wq = (const float*)d_in[1];
    const float* bq = (const float*)d_in[2];
    const float* wk = (const float*)d_in[3];
    const float* bk = (const float*)d_in[4];
    const float* wv = (const float*)d_in[5];
    const float* bv = (const float*)d_in[6];
    const float* wc = (const float*)d_in[7];
    const float* bc = (const float*)d_in[8];

    float* out      = (float*)d_out;
    float* out_attn = out;                                   // [B,S,D]
    float* out_w    = out + (size_t)BB*SS*DD;                // [B,H,S,S]
    float* out_k    = out_w + (size_t)BB*HH*SS*SS;           // [B,H,S,hd]
    float* out_v    = out_k + (size_t)BB*HH*SS*HD;           // [B,H,S,hd]

    __half *hsh, *wt, *qh, *kh, *vh, *apreh;
    cudaGetSymbolAddress((void**)&hsh,   g_hsh);
    cudaGetSymbolAddress((void**)&wt,    g_wt);
    cudaGetSymbolAddress((void**)&qh,    g_qh);
    cudaGetSymbolAddress((void**)&kh,    g_kh);
    cudaGetSymbolAddress((void**)&vh,    g_vh);
    cudaGetSymbolAddress((void**)&apreh, g_apreh);

    cudaFuncSetAttribute(gemm_qkv,
                         cudaFuncAttributeMaxDynamicSharedMemorySize, GEMM_SMEM);
    cudaFuncSetAttribute(gemm_c,
                         cudaFuncAttributeMaxDynamicSharedMemorySize, GEMM_SMEM);
    cudaFuncSetAttribute(fattn,
                         cudaFuncAttributeMaxDynamicSharedMemorySize, FATTN_SMEM);

    conv_h<<<(MM*DD/4)/256, 256>>>(hs, hsh);
    tconv4_h<<<dim3(DD/32, DD/32, 4), 256>>>(wq, wk, wv, wc, wt);

    gemm_qkv<<<dim3(DD/128, MM/128, 3), 256, GEMM_SMEM>>>(
        hsh, wt, bq, bk, bv, out_k, out_v, qh, kh, vh);

    fattn<<<dim3(SS/64, BB*HH), 256, FATTN_SMEM>>>(kh, vh, out_w);

    gemm_c<<<dim3(DD/128, MM/128), 256, GEMM_SMEM>>>(
        apreh, wt + 3*(size_t)DD*DD, bc, out_attn);
}